// round 14
// baseline (speedup 1.0000x reference)
#include <cuda_runtime.h>
#include <cuda_bf16.h>
#include <cstdint>
#include <math.h>

// Problem constants
#define B_  2
#define S_  2048
#define D_  1024
#define H_  16
#define DH_ 64
#define R_  8
#define M_  (B_*S_)          // 4096 rows

// Scratch (device globals; no allocation allowed)
__device__ __nv_bfloat16 g_x16[M_*D_];
__device__ float g_z[2*M_*R_];
__device__ __nv_bfloat16 g_q16[M_*D_];
__device__ __nv_bfloat16 g_k16[M_*D_];
__device__ __nv_bfloat16 g_v16[M_*D_];
__device__ __nv_bfloat16 g_attn16[M_*D_];
__device__ __nv_bfloat16 g_wq16[D_*D_];
__device__ __nv_bfloat16 g_wk16[D_*D_];
__device__ __nv_bfloat16 g_wv16[D_*D_];
__device__ __nv_bfloat16 g_wo16[D_*D_];

#define FULLMASK 0xffffffffu

// ===========================================================================
// PTX helpers
// ===========================================================================
__device__ __forceinline__ uint32_t smem_u32(const void* p) {
    uint32_t a;
    asm("{ .reg .u64 t; cvta.to.shared.u64 t, %1; cvt.u32.u64 %0, t; }"
        : "=r"(a) : "l"(p));
    return a;
}

#define LDSM4(R0,R1,R2,R3,ADDR) \
    asm volatile("ldmatrix.sync.aligned.m8n8.x4.shared.b16 {%0,%1,%2,%3}, [%4];" \
        : "=r"(R0), "=r"(R1), "=r"(R2), "=r"(R3) : "r"(ADDR))

#define LDSM4T(R0,R1,R2,R3,ADDR) \
    asm volatile("ldmatrix.sync.aligned.m8n8.x4.trans.shared.b16 {%0,%1,%2,%3}, [%4];" \
        : "=r"(R0), "=r"(R1), "=r"(R2), "=r"(R3) : "r"(ADDR))

#define MMA_BF16(C, A, B0, B1) \
    asm volatile("mma.sync.aligned.m16n8k16.row.col.f32.bf16.bf16.f32 " \
        "{%0,%1,%2,%3}, {%4,%5,%6,%7}, {%8,%9}, {%0,%1,%2,%3};" \
        : "+f"((C)[0]), "+f"((C)[1]), "+f"((C)[2]), "+f"((C)[3]) \
        : "r"((A)[0]), "r"((A)[1]), "r"((A)[2]), "r"((A)[3]), "r"(B0), "r"(B1))

#define CP16(DST, SRC) \
    asm volatile("cp.async.cg.shared.global [%0], [%1], 16;" :: "r"(DST), "l"(SRC))
#define CP_COMMIT() asm volatile("cp.async.commit_group;" ::: "memory")
#define CP_WAIT(N)  asm volatile("cp.async.wait_group %0;" :: "n"(N) : "memory")

__device__ __forceinline__ uint32_t pk_bf16x2(float a, float b) {
    __nv_bfloat162 t = __floats2bfloat162_rn(a, b);
    return *reinterpret_cast<uint32_t*>(&t);
}
__device__ __forceinline__ float rt_bf16(float a) {
    return __bfloat162float(__float2bfloat16(a));
}

// ---------------------------------------------------------------------------
// Prep: RMSNorm (blocks 0..M_-1) + weight conversion (blocks M_..M_+2047)
// ---------------------------------------------------------------------------
__global__ __launch_bounds__(256) void prep_kernel(
    const float* __restrict__ hs, const float* __restrict__ w,
    const float* __restrict__ Wq, const float* __restrict__ Wk,
    const float* __restrict__ Wv, const float* __restrict__ Wo,
    __nv_bfloat16* __restrict__ x16,
    __nv_bfloat16* __restrict__ wq16, __nv_bfloat16* __restrict__ wk16,
    __nv_bfloat16* __restrict__ wv16, __nv_bfloat16* __restrict__ wo16)
{
    int t = threadIdx.x;
    if (blockIdx.x < M_) {
        int row = blockIdx.x;
        const float* x = hs + (long)row * D_;
        float4 v = *(const float4*)&x[t * 4];
        float ss = v.x*v.x + v.y*v.y + v.z*v.z + v.w*v.w;
        #pragma unroll
        for (int o = 16; o > 0; o >>= 1) ss += __shfl_xor_sync(FULLMASK, ss, o);
        __shared__ float red[8];
        if ((t & 31) == 0) red[t >> 5] = ss;
        __syncthreads();
        __shared__ float s_inv;
        if (t == 0) {
            float s = 0.f;
            #pragma unroll
            for (int i = 0; i < 8; i++) s += red[i];
            s_inv = rsqrtf(s / (float)D_ + 1e-5f);
        }
        __syncthreads();
        float inv = s_inv;
        float4 wv4 = *(const float4*)&w[t * 4];
        uint2 o2;
        o2.x = pk_bf16x2(v.x * inv * wv4.x, v.y * inv * wv4.y);
        o2.y = pk_bf16x2(v.z * inv * wv4.z, v.w * inv * wv4.w);
        *(uint2*)&x16[(long)row * D_ + t * 4] = o2;
    } else {
        int bid2 = blockIdx.x - M_;
        int sel = bid2 >> 9;
        int ib  = bid2 & 511;
        const float* src = (sel == 0) ? Wq : (sel == 1) ? Wk : (sel == 2) ? Wv : Wo;
        __nv_bfloat16* dst = (sel == 0) ? wq16 : (sel == 1) ? wk16 : (sel == 2) ? wv16 : wo16;
        long idx = ((long)ib * 256 + t) * 8;
        float4 a = *(const float4*)&src[idx];
        float4 b = *(const float4*)&src[idx + 4];
        uint4 u;
        u.x = pk_bf16x2(a.x, a.y); u.y = pk_bf16x2(a.z, a.w);
        u.z = pk_bf16x2(b.x, b.y); u.w = pk_bf16x2(b.z, b.w);
        *(uint4*)&dst[idx] = u;
    }
}

// ---------------------------------------------------------------------------
// bf16 GEMM core: C[128x128] = A[*,1024] @ W[*,1024]^T.
// BK=64 bf16, 3-slot cp.async ring, ONE barrier per k-chunk.
// 8 warps x (32x64). MODE: 1 = fp32 + residual, 2 = bf16 out
// ---------------------------------------------------------------------------
#define RBW 144                     // 64 bf16 = 128B data + 16B pad
#define WTILE_B (128*RBW)           // 18432
#define GEMM_SMEM (6*WTILE_B)       // 110592

template <int MODE>
__device__ __forceinline__ void gemm128_bf16_core(
    const __nv_bfloat16* __restrict__ A, const __nv_bfloat16* __restrict__ W,
    const float* __restrict__ resid, float* __restrict__ C32,
    __nv_bfloat16* __restrict__ C16,
    int by, int bx, char* gsm)
{
    const uint32_t sA = smem_u32(gsm);
    const uint32_t sB = sA + 3 * WTILE_B;
    int tid = threadIdx.x;
    int lane = tid & 31;
    int w = tid >> 5;
    int wm = (w >> 1) * 32;
    int wn = (w & 1) * 64;

    const __nv_bfloat16* aP[4]; const __nv_bfloat16* bP[4];
    uint32_t stA[4], stB[4];
    #pragma unroll
    for (int l = 0; l < 4; l++) {
        int idx = tid + l * 256;
        int r = idx >> 3, c8 = idx & 7;
        aP[l] = A + (long)(by * 128 + r) * D_ + c8 * 8;
        bP[l] = W + (long)(bx * 128 + r) * D_ + c8 * 8;
        stA[l] = sA + r * RBW + c8 * 16;
        stB[l] = sB + r * RBW + c8 * 16;
    }

    float acc[2][8][4];
    #pragma unroll
    for (int mt = 0; mt < 2; mt++)
        #pragma unroll
        for (int nt = 0; nt < 8; nt++)
            #pragma unroll
            for (int j = 0; j < 4; j++) acc[mt][nt][j] = 0.f;

    const uint32_t aFragBase = sA + (wm + (lane & 15)) * RBW + (lane >> 4) * 16;
    const uint32_t bFragBase = sB +
        (wn + (lane & 7) + ((lane >> 4) << 3)) * RBW + ((lane >> 3) & 1) * 16;

    #pragma unroll
    for (int l = 0; l < 4; l++) { CP16(stA[l], aP[l]); CP16(stB[l], bP[l]); }
    CP_COMMIT();
    #pragma unroll
    for (int l = 0; l < 4; l++) {
        CP16(stA[l] + WTILE_B, aP[l] + 64);
        CP16(stB[l] + WTILE_B, bP[l] + 64);
    }
    CP_COMMIT();

    for (int kc = 0; kc < 16; kc++) {
        if (kc < 15) { CP_WAIT(1); } else { CP_WAIT(0); }
        __syncthreads();

        if (kc + 2 < 16) {
            int ns = (kc + 2) % 3;
            #pragma unroll
            for (int l = 0; l < 4; l++) {
                CP16(stA[l] + ns * WTILE_B, aP[l] + (kc + 2) * 64);
                CP16(stB[l] + ns * WTILE_B, bP[l] + (kc + 2) * 64);
            }
            CP_COMMIT();
        }

        int slot = kc % 3;
        uint32_t aBuf = aFragBase + slot * WTILE_B;
        uint32_t bBuf = bFragBase + slot * WTILE_B;

        #pragma unroll
        for (int ks = 0; ks < 4; ks++) {
            uint32_t af[2][4];
            uint32_t bf[8][2];
            #pragma unroll
            for (int mt = 0; mt < 2; mt++)
                LDSM4(af[mt][0], af[mt][1], af[mt][2], af[mt][3],
                      aBuf + mt * 16 * RBW + ks * 32);
            #pragma unroll
            for (int ntp = 0; ntp < 4; ntp++) {
                uint32_t r0, r1, r2, r3;
                LDSM4(r0, r1, r2, r3, bBuf + ntp * 16 * RBW + ks * 32);
                bf[2 * ntp][0] = r0; bf[2 * ntp][1] = r1;
                bf[2 * ntp + 1][0] = r2; bf[2 * ntp + 1][1] = r3;
            }
            #pragma unroll
            for (int mt = 0; mt < 2; mt++)
                #pragma unroll
                for (int nt = 0; nt < 8; nt++)
                    MMA_BF16(acc[mt][nt], af[mt], bf[nt][0], bf[nt][1]);
        }
    }

    #pragma unroll
    for (int mt = 0; mt < 2; mt++) {
        int row = by * 128 + wm + mt * 16 + (lane >> 2);
        int col = bx * 128 + wn + 2 * (lane & 3);
        #pragma unroll
        for (int nt = 0; nt < 8; nt++) {
            long i0 = (long)row * D_ + col + nt * 8;
            long i1 = i0 + 8 * D_;
            if (MODE == 2) {
                *(uint32_t*)&C16[i0] = pk_bf16x2(acc[mt][nt][0], acc[mt][nt][1]);
                *(uint32_t*)&C16[i1] = pk_bf16x2(acc[mt][nt][2], acc[mt][nt][3]);
            } else {
                float2 v0 = make_float2(acc[mt][nt][0], acc[mt][nt][1]);
                float2 v1 = make_float2(acc[mt][nt][2], acc[mt][nt][3]);
                float2 r0 = *(const float2*)&resid[i0];
                float2 r1 = *(const float2*)&resid[i1];
                v0.x += r0.x; v0.y += r0.y;
                v1.x += r1.x; v1.y += r1.y;
                *(float2*)&C32[i0] = v0;
                *(float2*)&C32[i1] = v1;
            }
        }
    }
}

__global__ __launch_bounds__(256, 2) void gemm_qkv_kernel(
    const __nv_bfloat16* __restrict__ A,
    const __nv_bfloat16* __restrict__ Wq, const __nv_bfloat16* __restrict__ Wk,
    const __nv_bfloat16* __restrict__ Wv,
    __nv_bfloat16* __restrict__ q16, __nv_bfloat16* __restrict__ k16,
    __nv_bfloat16* __restrict__ v16)
{
    extern __shared__ __align__(16) char gsm[];
    int wsel = blockIdx.x >> 3;
    int bx = blockIdx.x & 7;
    const __nv_bfloat16* W = (wsel == 0) ? Wq : (wsel == 1) ? Wk : Wv;
    __nv_bfloat16* C = (wsel == 0) ? q16 : (wsel == 1) ? k16 : v16;
    gemm128_bf16_core<2>(A, W, nullptr, nullptr, C, blockIdx.y, bx, gsm);
}

__global__ __launch_bounds__(256, 2) void gemm_o_kernel(
    const __nv_bfloat16* __restrict__ A, const __nv_bfloat16* __restrict__ W,
    const float* __restrict__ resid, float* __restrict__ C)
{
    extern __shared__ __align__(16) char gsm[];
    gemm128_bf16_core<1>(A, W, resid, C, nullptr, blockIdx.y, blockIdx.x, gsm);
}

// ---------------------------------------------------------------------------
// LoRA phase 1: z[row][:] = h[row] @ A   (h in bf16). Grid (M_/32, 2).
// ---------------------------------------------------------------------------
__global__ __launch_bounds__(256) void lora_z_kernel(
    const __nv_bfloat16* __restrict__ q16, const __nv_bfloat16* __restrict__ k16,
    const float* __restrict__ lora, float* __restrict__ z)
{
    int which = blockIdx.y;
    const __nv_bfloat16* h = which ? k16 : q16;
    int rowBase = blockIdx.x * 32;
    int b = rowBase / S_;
    const float* Ag = lora + ((long)which * B_ + b) * D_ * R_;

    __shared__ float As[R_ * D_];
    int tid = threadIdx.x;
    int lane = tid & 31, w = tid >> 5;

    #pragma unroll
    for (int k = 0; k < 4; k++) {
        int d = tid + k * 256;
        float4 a0 = *(const float4*)&Ag[d * R_];
        float4 a1 = *(const float4*)&Ag[d * R_ + 4];
        As[0*D_+d] = a0.x; As[1*D_+d] = a0.y; As[2*D_+d] = a0.z; As[3*D_+d] = a0.w;
        As[4*D_+d] = a1.x; As[5*D_+d] = a1.y; As[6*D_+d] = a1.z; As[7*D_+d] = a1.w;
    }
    __syncthreads();

    #pragma unroll
    for (int rr = 0; rr < 4; rr++) {
        int row = rowBase + w * 4 + rr;
        const __nv_bfloat16* hrow = h + (long)row * D_;
        float part[R_];
        #pragma unroll
        for (int r = 0; r < R_; r++) part[r] = 0.f;
        #pragma unroll
        for (int k = 0; k < 16; k++) {
            int d0 = lane * 2 + k * 64;
            __nv_bfloat162 hv2 = *(const __nv_bfloat162*)&hrow[d0];
            float h0 = __bfloat162float(hv2.x);
            float h1 = __bfloat162float(hv2.y);
            #pragma unroll
            for (int r = 0; r < R_; r++)
                part[r] += h0 * As[r * D_ + d0] + h1 * As[r * D_ + d0 + 1];
        }
        #pragma unroll
        for (int r = 0; r < R_; r++)
            #pragma unroll
            for (int o = 16; o > 0; o >>= 1)
                part[r] += __shfl_xor_sync(FULLMASK, part[r], o);
        if (lane == 0) {
            #pragma unroll
            for (int r = 0; r < R_; r++)
                z[((long)which * M_ + row) * R_ + r] = part[r];
        }
    }
}

// ---------------------------------------------------------------------------
// LoRA phase 2 (in place): h16 = bf16(h16 + 2*z@B^T). Grid (M_/16, 2).
// ---------------------------------------------------------------------------
#define LAR 16
__global__ __launch_bounds__(256) void lora_apply_kernel(
    __nv_bfloat16* __restrict__ q16, __nv_bfloat16* __restrict__ k16,
    const float* __restrict__ lora, const float* __restrict__ z)
{
    int which = blockIdx.y;
    __nv_bfloat16* g16 = which ? k16 : q16;
    int rowBase = blockIdx.x * LAR;
    int b = rowBase / S_;
    const float* Bg = lora + ((long)(2 + which) * B_ + b) * D_ * R_;

    __shared__ float zs[LAR][R_];
    int tid = threadIdx.x;
    if (tid < LAR * R_)
        zs[tid >> 3][tid & 7] = z[((long)which * M_ + rowBase + (tid >> 3)) * R_ + (tid & 7)];
    __syncthreads();

    int d0 = tid * 4;
    float br[4][R_];
    #pragma unroll
    for (int j = 0; j < 4; j++) {
        float4 b0 = *(const float4*)&Bg[(d0 + j) * R_];
        float4 b1 = *(const float4*)&Bg[(d0 + j) * R_ + 4];
        br[j][0] = b0.x; br[j][1] = b0.y; br[j][2] = b0.z; br[j][3] = b0.w;
        br[j][4] = b1.x; br[j][5] = b1.y; br[j][6] = b1.z; br[j][7] = b1.w;
    }

    #pragma unroll 4
    for (int rr = 0; rr < LAR; rr++) {
        long idx = (long)(rowBase + rr) * D_ + d0;
        uint2 hraw = *(const uint2*)&g16[idx];
        __nv_bfloat162 p0 = *(__nv_bfloat162*)&hraw.x;
        __nv_bfloat162 p1 = *(__nv_bfloat162*)&hraw.y;
        float hv[4] = { __bfloat162float(p0.x), __bfloat162float(p0.y),
                        __bfloat162float(p1.x), __bfloat162float(p1.y) };
        float del[4];
        #pragma unroll
        for (int j = 0; j < 4; j++) {
            float s = 0.f;
            #pragma unroll
            for (int r = 0; r < R_; r++) s += zs[rr][r] * br[j][r];
            del[j] = s;
        }
        uint2 o2;
        o2.x = pk_bf16x2(hv[0] + 2.f * del[0], hv[1] + 2.f * del[1]);
        o2.y = pk_bf16x2(hv[2] + 2.f * del[2], hv[3] + 2.f * del[3]);
        *(uint2*)&g16[idx] = o2;
    }
}

// ---------------------------------------------------------------------------
// Flash attention, bf16 mma, causal. Q tile 64, K/V tile 64, 128 threads,
// 3 CTAs/SM. P in registers (C-frag == A-frag identity).
// ---------------------------------------------------------------------------
#define RB 144
#define KSLOT_B (64 * RB)
#define FQ_B  (64 * RB)
#define FLASH_SMEM (FQ_B + 3*KSLOT_B + 3*KSLOT_B)   // 64512

__global__ __launch_bounds__(128, 3) void flash_mma_kernel(
    const __nv_bfloat16* __restrict__ Q, const __nv_bfloat16* __restrict__ K,
    const __nv_bfloat16* __restrict__ V, __nv_bfloat16* __restrict__ O16)
{
    extern __shared__ __align__(16) char smc[];
    const uint32_t qsB = smem_u32(smc);
    const uint32_t ksB = qsB + FQ_B;
    const uint32_t vnB = ksB + 3 * KSLOT_B;

    int qi = (gridDim.x - 1) - blockIdx.x;   // heavy tiles first
    int h  = blockIdx.y;
    int b  = blockIdx.z;
    int tid = threadIdx.x;
    int lane = tid & 31;
    int w = tid >> 5;

    int cKp[4], cC[4];
    #pragma unroll
    for (int l = 0; l < 4; l++) {
        int idx = tid + l * 128;
        cKp[l] = idx >> 3; cC[l] = idx & 7;
    }

    const __nv_bfloat16* Qp = Q + (long)(b * S_ + qi * 64) * D_ + h * DH_;
    #pragma unroll
    for (int l = 0; l < 4; l++) {
        int idx = tid + l * 128;
        int q = idx >> 3, c8 = idx & 7;
        float4 v = *(const float4*)&Qp[(long)q * D_ + c8 * 8];
        asm volatile("st.shared.v4.b32 [%0], {%1,%2,%3,%4};" ::
            "r"(qsB + q * RB + c8 * 16),
            "r"(__float_as_uint(v.x)), "r"(__float_as_uint(v.y)),
            "r"(__float_as_uint(v.z)), "r"(__float_as_uint(v.w)) : "memory");
    }
    {
        const __nv_bfloat16* Kp = K + (long)(b * S_) * D_ + h * DH_;
        const __nv_bfloat16* Vp = V + (long)(b * S_) * D_ + h * DH_;
        #pragma unroll
        for (int l = 0; l < 4; l++) {
            CP16(ksB + cKp[l] * RB + cC[l] * 16, Kp + (long)cKp[l] * D_ + cC[l] * 8);
            CP16(vnB + cKp[l] * RB + cC[l] * 16, Vp + (long)cKp[l] * D_ + cC[l] * 8);
        }
        CP_COMMIT();
    }

    float o[8][4];
    #pragma unroll
    for (int nt = 0; nt < 8; nt++)
        #pragma unroll
        for (int j = 0; j < 4; j++) o[nt][j] = 0.f;
    float m0 = -1e30f, m1 = -1e30f, l0 = 0.f, l1 = 0.f;

    const uint32_t kFragOff = ((lane & 7) + ((lane >> 4) << 3)) * RB + ((lane >> 3) & 1) * 16;
    const uint32_t vFragOff = ((lane & 7) + ((lane >> 3) & 1) * 8) * RB + (lane >> 4) * 16;

    bool qfLoaded = false;
    uint32_t qf[4][4];

    const float SC = 0.125f * 1.44269504f;

    int ktmax = qi + 1;
    for (int kt = 0; kt < ktmax; kt++) {
        int slot = kt % 3;
        bool havenext = (kt + 1) < ktmax;

        if (havenext) {
            int ns = (kt + 1) % 3;
            const __nv_bfloat16* Kp = K + (long)(b * S_ + (kt + 1) * 64) * D_ + h * DH_;
            const __nv_bfloat16* Vp = V + (long)(b * S_ + (kt + 1) * 64) * D_ + h * DH_;
            uint32_t kd = ksB + ns * KSLOT_B, vd = vnB + ns * KSLOT_B;
            #pragma unroll
            for (int l = 0; l < 4; l++) {
                CP16(kd + cKp[l] * RB + cC[l] * 16, Kp + (long)cKp[l] * D_ + cC[l] * 8);
                CP16(vd + cKp[l] * RB + cC[l] * 16, Vp + (long)cKp[l] * D_ + cC[l] * 8);
            }
            CP_COMMIT();
            CP_WAIT(1);
        } else {
            CP_WAIT(0);
        }
        __syncthreads();

        if (!qfLoaded) {
            uint32_t base = qsB + (w * 16 + (lane & 15)) * RB + (lane >> 4) * 16;
            #pragma unroll
            for (int ds = 0; ds < 4; ds++)
                LDSM4(qf[ds][0], qf[ds][1], qf[ds][2], qf[ds][3], base + ds * 32);
            qfLoaded = true;
        }

        {
            const uint32_t kBase = ksB + slot * KSLOT_B + kFragOff;
            const uint32_t vBase = vnB + slot * KSLOT_B + vFragOff;

            float s[8][4];
            #pragma unroll
            for (int nt = 0; nt < 8; nt++)
                #pragma unroll
                for (int j = 0; j < 4; j++) s[nt][j] = 0.f;

            #pragma unroll
            for (int ds = 0; ds < 4; ds++) {
                uint32_t bf[8][2];
                #pragma unroll
                for (int ntp = 0; ntp < 4; ntp++) {
                    uint32_t r0, r1, r2, r3;
                    LDSM4(r0, r1, r2, r3, kBase + ntp * 16 * RB + ds * 32);
                    bf[2 * ntp][0] = r0; bf[2 * ntp][1] = r1;
                    bf[2 * ntp + 1][0] = r2; bf[2 * ntp + 1][1] = r3;
                }
                #pragma unroll
                for (int nt = 0; nt < 8; nt++)
                    MMA_BF16(s[nt], qf[ds], bf[nt][0], bf[nt][1]);
            }

            bool needmask = (kt * 64 + 63) > (qi * 64 + w * 16);
            int row0 = qi * 64 + w * 16 + (lane >> 2);
            float ml0 = -1e30f, ml1 = -1e30f;
            #pragma unroll
            for (int nt = 0; nt < 8; nt++) {
                #pragma unroll
                for (int j = 0; j < 4; j++) {
                    float v = s[nt][j] * SC;
                    if (needmask) {
                        int col = kt * 64 + nt * 8 + 2 * (lane & 3) + (j & 1);
                        int row = row0 + ((j >> 1) << 3);
                        if (col > row) v = -1e30f;
                    }
                    s[nt][j] = v;
                }
                ml0 = fmaxf(ml0, fmaxf(s[nt][0], s[nt][1]));
                ml1 = fmaxf(ml1, fmaxf(s[nt][2], s[nt][3]));
            }
            ml0 = fmaxf(ml0, __shfl_xor_sync(FULLMASK, ml0, 1));
            ml0 = fmaxf(ml0, __shfl_xor_sync(FULLMASK, ml0, 2));
            ml1 = fmaxf(ml1, __shfl_xor_sync(FULLMASK, ml1, 1));
            ml1 = fmaxf(ml1, __shfl_xor_sync(FULLMASK, ml1, 2));
            float mn0 = fmaxf(m0, ml0), mn1 = fmaxf(m1, ml1);
            float a0 = exp2f(m0 - mn0), a1 = exp2f(m1 - mn1);
            float sum0 = 0.f, sum1 = 0.f;
            #pragma unroll
            for (int nt = 0; nt < 8; nt++) {
                s[nt][0] = rt_bf16(exp2f(s[nt][0] - mn0));
                s[nt][1] = rt_bf16(exp2f(s[nt][1] - mn0));
                s[nt][2] = rt_bf16(exp2f(s[nt][2] - mn1));
                s[nt][3] = rt_bf16(exp2f(s[nt][3] - mn1));
                sum0 += s[nt][0] + s[nt][1];
                sum1 += s[nt][2] + s[nt][3];
            }
            sum0 += __shfl_xor_sync(FULLMASK, sum0, 1);
            sum0 += __shfl_xor_sync(FULLMASK, sum0, 2);
            sum1 += __shfl_xor_sync(FULLMASK, sum1, 1);
            sum1 += __shfl_xor_sync(FULLMASK, sum1, 2);
            l0 = l0 * a0 + sum0;
            l1 = l1 * a1 + sum1;
            m0 = mn0; m1 = mn1;
            #pragma unroll
            for (int nt = 0; nt < 8; nt++) {
                o[nt][0] *= a0; o[nt][1] *= a0;
                o[nt][2] *= a1; o[nt][3] *= a1;
            }

            #pragma unroll
            for (int ks = 0; ks < 4; ks++) {
                uint32_t pf[4];
                pf[0] = pk_bf16x2(s[2*ks][0],   s[2*ks][1]);
                pf[1] = pk_bf16x2(s[2*ks][2],   s[2*ks][3]);
                pf[2] = pk_bf16x2(s[2*ks+1][0], s[2*ks+1][1]);
                pf[3] = pk_bf16x2(s[2*ks+1][2], s[2*ks+1][3]);
                uint32_t vf[8][2];
                #pragma unroll
                for (int ntp = 0; ntp < 4; ntp++) {
                    uint32_t r0, r1, r2, r3;
                    LDSM4T(r0, r1, r2, r3, vBase + ks * 16 * RB + ntp * 32);
                    vf[2 * ntp][0] = r0; vf[2 * ntp][1] = r1;
                    vf[2 * ntp + 1][0] = r2; vf[2 * ntp + 1][1] = r3;
                }
                #pragma unroll
                for (int nt = 0; nt < 8; nt++)
                    MMA_BF16(o[nt], pf, vf[nt][0], vf[nt][1]);
            }
        }
    }

    float inv0 = 1.f / l0, inv1 = 1.f / l1;
    int row0 = qi * 64 + w * 16 + (lane >> 2);
    long base0 = (long)(b * S_ + row0) * D_ + h * DH_ + 2 * (lane & 3);
    long base1 = base0 + 8 * D_;
    #pragma unroll
    for (int nt = 0; nt < 8; nt++) {
        *(uint32_t*)&O16[base0 + nt * 8] = pk_bf16x2(o[nt][0] * inv0, o[nt][1] * inv0);
        *(uint32_t*)&O16[base1 + nt * 8] = pk_bf16x2(o[nt][2] * inv1, o[nt][3] * inv1);
    }
}

// ---------------------------------------------------------------------------
// Launch
// ---------------------------------------------------------------------------
extern "C" void kernel_launch(void* const* d_in, const int* in_sizes, int n_in,
                              void* d_out, int out_size)
{
    const float* hidden = (const float*)d_in[0];
    // d_in[1] = attention_mask: causal tril -> handled analytically
    const float* lora   = (const float*)d_in[2];   // [4, B, D, R]
    const float* ln_w   = (const float*)d_in[3];
    const float* Wq     = (const float*)d_in[4];
    const float* Wk     = (const float*)d_in[5];
    const float* Wv     = (const float*)d_in[6];
    const float* Wo     = (const float*)d_in[7];
    float* out = (float*)d_out;

    float *z;
    __nv_bfloat16 *x16, *q16, *k16, *v16, *attn16, *wq16, *wk16, *wv16, *wo16;
    cudaGetSymbolAddress((void**)&x16,    g_x16);
    cudaGetSymbolAddress((void**)&z,      g_z);
    cudaGetSymbolAddress((void**)&q16,    g_q16);
    cudaGetSymbolAddress((void**)&k16,    g_k16);
    cudaGetSymbolAddress((void**)&v16,    g_v16);
    cudaGetSymbolAddress((void**)&attn16, g_attn16);
    cudaGetSymbolAddress((void**)&wq16,   g_wq16);
    cudaGetSymbolAddress((void**)&wk16,   g_wk16);
    cudaGetSymbolAddress((void**)&wv16,   g_wv16);
    cudaGetSymbolAddress((void**)&wo16,   g_wo16);

    cudaFuncSetAttribute(gemm_qkv_kernel, cudaFuncAttributeMaxDynamicSharedMemorySize, GEMM_SMEM);
    cudaFuncSetAttribute(gemm_o_kernel,   cudaFuncAttributeMaxDynamicSharedMemorySize, GEMM_SMEM);
    cudaFuncSetAttribute(flash_mma_kernel, cudaFuncAttributeMaxDynamicSharedMemorySize, FLASH_SMEM);

    // 0+1. RMSNorm (-> bf16) + weight conversion
    prep_kernel<<<M_ + 2048, 256>>>(hidden, ln_w, Wq, Wk, Wv, Wo,
                                    x16, wq16, wk16, wv16, wo16);

    // 2. Fused QKV projections (all outputs bf16)
    dim3 gq(24, M_ / 128);
    gemm_qkv_kernel<<<gq, 256, GEMM_SMEM>>>(x16, wq16, wk16, wv16, q16, k16, v16);

    // 3. LoRA: z = h@A (bf16 h), then h += 2 z@B^T in place
    dim3 gl(M_ / 32, 2);
    lora_z_kernel<<<gl, 256>>>(q16, k16, lora, z);
    dim3 gla(M_ / LAR, 2);
    lora_apply_kernel<<<gla, 256>>>(q16, k16, lora, z);

    // 4. Causal flash attention (bf16 in/out)
    dim3 fg(S_ / 64, H_, B_);
    flash_mma_kernel<<<fg, 128, FLASH_SMEM>>>(q16, k16, v16, attn16);

    // 5. Output projection + residual (bf16 in, fp32 out)
    dim3 go(8, M_ / 128);
    gemm_o_kernel<<<go, 256, GEMM_SMEM>>>(attn16, wo16, hidden, out);
}

// round 15
// speedup vs baseline: 1.0670x; 1.0670x over previous
#include <cuda_runtime.h>
#include <cuda_bf16.h>
#include <cstdint>
#include <math.h>

// Problem constants
#define B_  2
#define S_  2048
#define D_  1024
#define H_  16
#define DH_ 64
#define R_  8
#define M_  (B_*S_)          // 4096 rows

// Scratch (device globals; no allocation allowed)
__device__ __nv_bfloat16 g_x16[M_*D_];
__device__ float g_hq[M_*D_];
__device__ float g_hk[M_*D_];
__device__ float g_z[2*M_*R_];
__device__ __nv_bfloat16 g_q16[M_*D_];
__device__ __nv_bfloat16 g_k16[M_*D_];
__device__ __nv_bfloat16 g_v16[M_*D_];
__device__ __nv_bfloat16 g_attn16[M_*D_];
__device__ __nv_bfloat16 g_wq16[D_*D_];
__device__ __nv_bfloat16 g_wk16[D_*D_];
__device__ __nv_bfloat16 g_wv16[D_*D_];
__device__ __nv_bfloat16 g_wo16[D_*D_];

#define FULLMASK 0xffffffffu

// ===========================================================================
// PTX helpers
// ===========================================================================
__device__ __forceinline__ uint32_t smem_u32(const void* p) {
    uint32_t a;
    asm("{ .reg .u64 t; cvta.to.shared.u64 t, %1; cvt.u32.u64 %0, t; }"
        : "=r"(a) : "l"(p));
    return a;
}

#define LDSM4(R0,R1,R2,R3,ADDR) \
    asm volatile("ldmatrix.sync.aligned.m8n8.x4.shared.b16 {%0,%1,%2,%3}, [%4];" \
        : "=r"(R0), "=r"(R1), "=r"(R2), "=r"(R3) : "r"(ADDR))

#define LDSM4T(R0,R1,R2,R3,ADDR) \
    asm volatile("ldmatrix.sync.aligned.m8n8.x4.trans.shared.b16 {%0,%1,%2,%3}, [%4];" \
        : "=r"(R0), "=r"(R1), "=r"(R2), "=r"(R3) : "r"(ADDR))

#define MMA_BF16(C, A, B0, B1) \
    asm volatile("mma.sync.aligned.m16n8k16.row.col.f32.bf16.bf16.f32 " \
        "{%0,%1,%2,%3}, {%4,%5,%6,%7}, {%8,%9}, {%0,%1,%2,%3};" \
        : "+f"((C)[0]), "+f"((C)[1]), "+f"((C)[2]), "+f"((C)[3]) \
        : "r"((A)[0]), "r"((A)[1]), "r"((A)[2]), "r"((A)[3]), "r"(B0), "r"(B1))

#define CP16(DST, SRC) \
    asm volatile("cp.async.cg.shared.global [%0], [%1], 16;" :: "r"(DST), "l"(SRC))
#define CP_COMMIT() asm volatile("cp.async.commit_group;" ::: "memory")
#define CP_WAIT(N)  asm volatile("cp.async.wait_group %0;" :: "n"(N) : "memory")

__device__ __forceinline__ uint32_t pk_bf16x2(float a, float b) {
    __nv_bfloat162 t = __floats2bfloat162_rn(a, b);
    return *reinterpret_cast<uint32_t*>(&t);
}
__device__ __forceinline__ float rt_bf16(float a) {
    return __bfloat162float(__float2bfloat16(a));
}

// ---------------------------------------------------------------------------
// Prep: RMSNorm (blocks 0..M_-1) + weight conversion (blocks M_..M_+2047)
// ---------------------------------------------------------------------------
__global__ __launch_bounds__(256) void prep_kernel(
    const float* __restrict__ hs, const float* __restrict__ w,
    const float* __restrict__ Wq, const float* __restrict__ Wk,
    const float* __restrict__ Wv, const float* __restrict__ Wo,
    __nv_bfloat16* __restrict__ x16,
    __nv_bfloat16* __restrict__ wq16, __nv_bfloat16* __restrict__ wk16,
    __nv_bfloat16* __restrict__ wv16, __nv_bfloat16* __restrict__ wo16)
{
    int t = threadIdx.x;
    if (blockIdx.x < M_) {
        int row = blockIdx.x;
        const float* x = hs + (long)row * D_;
        float4 v = *(const float4*)&x[t * 4];
        float ss = v.x*v.x + v.y*v.y + v.z*v.z + v.w*v.w;
        #pragma unroll
        for (int o = 16; o > 0; o >>= 1) ss += __shfl_xor_sync(FULLMASK, ss, o);
        __shared__ float red[8];
        if ((t & 31) == 0) red[t >> 5] = ss;
        __syncthreads();
        __shared__ float s_inv;
        if (t == 0) {
            float s = 0.f;
            #pragma unroll
            for (int i = 0; i < 8; i++) s += red[i];
            s_inv = rsqrtf(s / (float)D_ + 1e-5f);
        }
        __syncthreads();
        float inv = s_inv;
        float4 wv4 = *(const float4*)&w[t * 4];
        uint2 o2;
        o2.x = pk_bf16x2(v.x * inv * wv4.x, v.y * inv * wv4.y);
        o2.y = pk_bf16x2(v.z * inv * wv4.z, v.w * inv * wv4.w);
        *(uint2*)&x16[(long)row * D_ + t * 4] = o2;
    } else {
        int bid2 = blockIdx.x - M_;
        int sel = bid2 >> 9;
        int ib  = bid2 & 511;
        const float* src = (sel == 0) ? Wq : (sel == 1) ? Wk : (sel == 2) ? Wv : Wo;
        __nv_bfloat16* dst = (sel == 0) ? wq16 : (sel == 1) ? wk16 : (sel == 2) ? wv16 : wo16;
        long idx = ((long)ib * 256 + t) * 8;
        float4 a = *(const float4*)&src[idx];
        float4 b = *(const float4*)&src[idx + 4];
        uint4 u;
        u.x = pk_bf16x2(a.x, a.y); u.y = pk_bf16x2(a.z, a.w);
        u.z = pk_bf16x2(b.x, b.y); u.w = pk_bf16x2(b.z, b.w);
        *(uint4*)&dst[idx] = u;
    }
}

// ---------------------------------------------------------------------------
// bf16 GEMM core: C[128x128] = A[*,1024] @ W[*,1024]^T.
// BK=64 bf16, 3-slot cp.async ring, ONE barrier per k-chunk.
// 8 warps x (32x64). MODE: 0 = fp32 out, 1 = fp32 + residual, 2 = bf16 out
// ---------------------------------------------------------------------------
#define RBW 144                     // 64 bf16 = 128B data + 16B pad
#define WTILE_B (128*RBW)           // 18432
#define GEMM_SMEM (6*WTILE_B)       // 110592 (3 slots A + 3 slots B)

template <int MODE>
__device__ __forceinline__ void gemm128_bf16_core(
    const __nv_bfloat16* __restrict__ A, const __nv_bfloat16* __restrict__ W,
    const float* __restrict__ resid, float* __restrict__ C32,
    __nv_bfloat16* __restrict__ C16,
    int by, int bx, char* gsm)
{
    const uint32_t sA = smem_u32(gsm);
    const uint32_t sB = sA + 3 * WTILE_B;
    int tid = threadIdx.x;
    int lane = tid & 31;
    int w = tid >> 5;
    int wm = (w >> 1) * 32;
    int wn = (w & 1) * 64;

    const __nv_bfloat16* aP[4]; const __nv_bfloat16* bP[4];
    uint32_t stA[4], stB[4];
    #pragma unroll
    for (int l = 0; l < 4; l++) {
        int idx = tid + l * 256;
        int r = idx >> 3, c8 = idx & 7;
        aP[l] = A + (long)(by * 128 + r) * D_ + c8 * 8;
        bP[l] = W + (long)(bx * 128 + r) * D_ + c8 * 8;
        stA[l] = sA + r * RBW + c8 * 16;
        stB[l] = sB + r * RBW + c8 * 16;
    }

    float acc[2][8][4];
    #pragma unroll
    for (int mt = 0; mt < 2; mt++)
        #pragma unroll
        for (int nt = 0; nt < 8; nt++)
            #pragma unroll
            for (int j = 0; j < 4; j++) acc[mt][nt][j] = 0.f;

    const uint32_t aFragBase = sA + (wm + (lane & 15)) * RBW + (lane >> 4) * 16;
    const uint32_t bFragBase = sB +
        (wn + (lane & 7) + ((lane >> 4) << 3)) * RBW + ((lane >> 3) & 1) * 16;

    // Prologue: stage chunks 0 and 1
    #pragma unroll
    for (int l = 0; l < 4; l++) { CP16(stA[l], aP[l]); CP16(stB[l], bP[l]); }
    CP_COMMIT();
    #pragma unroll
    for (int l = 0; l < 4; l++) {
        CP16(stA[l] + WTILE_B, aP[l] + 64);
        CP16(stB[l] + WTILE_B, bP[l] + 64);
    }
    CP_COMMIT();

    for (int kc = 0; kc < 16; kc++) {          // D/64
        if (kc < 15) { CP_WAIT(1); } else { CP_WAIT(0); }
        __syncthreads();

        if (kc + 2 < 16) {
            int ns = (kc + 2) % 3;
            #pragma unroll
            for (int l = 0; l < 4; l++) {
                CP16(stA[l] + ns * WTILE_B, aP[l] + (kc + 2) * 64);
                CP16(stB[l] + ns * WTILE_B, bP[l] + (kc + 2) * 64);
            }
            CP_COMMIT();
        }

        int slot = kc % 3;
        uint32_t aBuf = aFragBase + slot * WTILE_B;
        uint32_t bBuf = bFragBase + slot * WTILE_B;

        #pragma unroll
        for (int ks = 0; ks < 4; ks++) {
            uint32_t af[2][4];
            uint32_t bf[8][2];
            #pragma unroll
            for (int mt = 0; mt < 2; mt++)
                LDSM4(af[mt][0], af[mt][1], af[mt][2], af[mt][3],
                      aBuf + mt * 16 * RBW + ks * 32);
            #pragma unroll
            for (int ntp = 0; ntp < 4; ntp++) {
                uint32_t r0, r1, r2, r3;
                LDSM4(r0, r1, r2, r3, bBuf + ntp * 16 * RBW + ks * 32);
                bf[2 * ntp][0] = r0; bf[2 * ntp][1] = r1;
                bf[2 * ntp + 1][0] = r2; bf[2 * ntp + 1][1] = r3;
            }
            #pragma unroll
            for (int mt = 0; mt < 2; mt++)
                #pragma unroll
                for (int nt = 0; nt < 8; nt++)
                    MMA_BF16(acc[mt][nt], af[mt], bf[nt][0], bf[nt][1]);
        }
    }

    #pragma unroll
    for (int mt = 0; mt < 2; mt++) {
        int row = by * 128 + wm + mt * 16 + (lane >> 2);
        int col = bx * 128 + wn + 2 * (lane & 3);
        #pragma unroll
        for (int nt = 0; nt < 8; nt++) {
            long i0 = (long)row * D_ + col + nt * 8;
            long i1 = i0 + 8 * D_;
            if (MODE == 2) {
                *(uint32_t*)&C16[i0] = pk_bf16x2(acc[mt][nt][0], acc[mt][nt][1]);
                *(uint32_t*)&C16[i1] = pk_bf16x2(acc[mt][nt][2], acc[mt][nt][3]);
            } else {
                float2 v0 = make_float2(acc[mt][nt][0], acc[mt][nt][1]);
                float2 v1 = make_float2(acc[mt][nt][2], acc[mt][nt][3]);
                if (MODE == 1) {
                    float2 r0 = *(const float2*)&resid[i0];
                    float2 r1 = *(const float2*)&resid[i1];
                    v0.x += r0.x; v0.y += r0.y;
                    v1.x += r1.x; v1.y += r1.y;
                }
                *(float2*)&C32[i0] = v0;
                *(float2*)&C32[i1] = v1;
            }
        }
    }
}

__global__ __launch_bounds__(256, 2) void gemm_qkv_kernel(
    const __nv_bfloat16* __restrict__ A,
    const __nv_bfloat16* __restrict__ Wq, const __nv_bfloat16* __restrict__ Wk,
    const __nv_bfloat16* __restrict__ Wv,
    float* __restrict__ hq, float* __restrict__ hk, __nv_bfloat16* __restrict__ v16)
{
    extern __shared__ __align__(16) char gsm[];
    int wsel = blockIdx.x >> 3;
    int bx = blockIdx.x & 7;
    if (wsel == 0)
        gemm128_bf16_core<0>(A, Wq, nullptr, hq, nullptr, blockIdx.y, bx, gsm);
    else if (wsel == 1)
        gemm128_bf16_core<0>(A, Wk, nullptr, hk, nullptr, blockIdx.y, bx, gsm);
    else
        gemm128_bf16_core<2>(A, Wv, nullptr, nullptr, v16, blockIdx.y, bx, gsm);
}

__global__ __launch_bounds__(256, 2) void gemm_o_kernel(
    const __nv_bfloat16* __restrict__ A, const __nv_bfloat16* __restrict__ W,
    const float* __restrict__ resid, float* __restrict__ C)
{
    extern __shared__ __align__(16) char gsm[];
    gemm128_bf16_core<1>(A, W, resid, C, nullptr, blockIdx.y, blockIdx.x, gsm);
}

// ---------------------------------------------------------------------------
// LoRA phase 1: z[row][:] = h[row] @ A   (grid: (M_/32, 2), 256 threads)
// ---------------------------------------------------------------------------
__global__ __launch_bounds__(256) void lora_z_kernel(
    const float* __restrict__ hq, const float* __restrict__ hk,
    const float* __restrict__ lora, float* __restrict__ z)
{
    int which = blockIdx.y;
    const float* h = which ? hk : hq;
    int rowBase = blockIdx.x * 32;
    int b = rowBase / S_;
    const float* Ag = lora + ((long)which * B_ + b) * D_ * R_;

    __shared__ float As[R_ * D_];
    int tid = threadIdx.x;
    int lane = tid & 31, w = tid >> 5;

    #pragma unroll
    for (int k = 0; k < 4; k++) {
        int d = tid + k * 256;
        float4 a0 = *(const float4*)&Ag[d * R_];
        float4 a1 = *(const float4*)&Ag[d * R_ + 4];
        As[0*D_+d] = a0.x; As[1*D_+d] = a0.y; As[2*D_+d] = a0.z; As[3*D_+d] = a0.w;
        As[4*D_+d] = a1.x; As[5*D_+d] = a1.y; As[6*D_+d] = a1.z; As[7*D_+d] = a1.w;
    }
    __syncthreads();

    #pragma unroll
    for (int rr = 0; rr < 4; rr++) {
        int row = rowBase + w * 4 + rr;
        const float* hrow = h + (long)row * D_;
        float part[R_];
        #pragma unroll
        for (int r = 0; r < R_; r++) part[r] = 0.f;
        #pragma unroll
        for (int k = 0; k < 32; k++) {
            int d = lane + k * 32;
            float hv = hrow[d];
            #pragma unroll
            for (int r = 0; r < R_; r++) part[r] += hv * As[r * D_ + d];
        }
        #pragma unroll
        for (int r = 0; r < R_; r++)
            #pragma unroll
            for (int o = 16; o > 0; o >>= 1)
                part[r] += __shfl_xor_sync(FULLMASK, part[r], o);
        if (lane == 0) {
            #pragma unroll
            for (int r = 0; r < R_; r++)
                z[((long)which * M_ + row) * R_ + r] = part[r];
        }
    }
}

// ---------------------------------------------------------------------------
// LoRA phase 2: g16 = bf16(h + 2*z@B^T). Grid (M_/16, 2), 256 threads.
// ---------------------------------------------------------------------------
#define LAR 16
__global__ __launch_bounds__(256) void lora_apply_kernel(
    const float* __restrict__ hq, const float* __restrict__ hk,
    __nv_bfloat16* __restrict__ q16, __nv_bfloat16* __restrict__ k16,
    const float* __restrict__ lora, const float* __restrict__ z)
{
    int which = blockIdx.y;
    const float* h = which ? hk : hq;
    __nv_bfloat16* g16 = which ? k16 : q16;
    int rowBase = blockIdx.x * LAR;
    int b = rowBase / S_;
    const float* Bg = lora + ((long)(2 + which) * B_ + b) * D_ * R_;

    __shared__ float zs[LAR][R_];
    int tid = threadIdx.x;
    if (tid < LAR * R_)
        zs[tid >> 3][tid & 7] = z[((long)which * M_ + rowBase + (tid >> 3)) * R_ + (tid & 7)];
    __syncthreads();

    int d0 = tid * 4;
    float br[4][R_];
    #pragma unroll
    for (int j = 0; j < 4; j++) {
        float4 b0 = *(const float4*)&Bg[(d0 + j) * R_];
        float4 b1 = *(const float4*)&Bg[(d0 + j) * R_ + 4];
        br[j][0] = b0.x; br[j][1] = b0.y; br[j][2] = b0.z; br[j][3] = b0.w;
        br[j][4] = b1.x; br[j][5] = b1.y; br[j][6] = b1.z; br[j][7] = b1.w;
    }

    #pragma unroll 4
    for (int rr = 0; rr < LAR; rr++) {
        long idx = (long)(rowBase + rr) * D_ + d0;
        float4 hv = *(const float4*)&h[idx];
        float del[4];
        #pragma unroll
        for (int j = 0; j < 4; j++) {
            float s = 0.f;
            #pragma unroll
            for (int r = 0; r < R_; r++) s += zs[rr][r] * br[j][r];
            del[j] = s;
        }
        uint2 o2;
        o2.x = pk_bf16x2(hv.x + 2.f * del[0], hv.y + 2.f * del[1]);
        o2.y = pk_bf16x2(hv.z + 2.f * del[2], hv.w + 2.f * del[3]);
        *(uint2*)&g16[idx] = o2;
    }
}

// ---------------------------------------------------------------------------
// Flash attention, bf16 mma, causal. Q tile 64, K/V tile 64, 128 threads,
// 3 CTAs/SM. P kept in registers (C-frag == A-frag layout identity).
// smem = 9216(Q) + 3x9216(K) + 3x9216(V) = 64512
// ---------------------------------------------------------------------------
#define RB 144
#define KSLOT_B (64 * RB)
#define FQ_B  (64 * RB)
#define FLASH_SMEM (FQ_B + 3*KSLOT_B + 3*KSLOT_B)   // 64512

__global__ __launch_bounds__(128, 3) void flash_mma_kernel(
    const __nv_bfloat16* __restrict__ Q, const __nv_bfloat16* __restrict__ K,
    const __nv_bfloat16* __restrict__ V, __nv_bfloat16* __restrict__ O16)
{
    extern __shared__ __align__(16) char smc[];
    const uint32_t qsB = smem_u32(smc);
    const uint32_t ksB = qsB + FQ_B;
    const uint32_t vnB = ksB + 3 * KSLOT_B;

    int qi = (gridDim.x - 1) - blockIdx.x;   // heavy tiles first
    int h  = blockIdx.y;
    int b  = blockIdx.z;
    int tid = threadIdx.x;
    int lane = tid & 31;
    int w = tid >> 5;

    int cKp[4], cC[4];
    #pragma unroll
    for (int l = 0; l < 4; l++) {
        int idx = tid + l * 128;
        cKp[l] = idx >> 3; cC[l] = idx & 7;
    }

    const __nv_bfloat16* Qp = Q + (long)(b * S_ + qi * 64) * D_ + h * DH_;
    #pragma unroll
    for (int l = 0; l < 4; l++) {
        int idx = tid + l * 128;
        int q = idx >> 3, c8 = idx & 7;
        float4 v = *(const float4*)&Qp[(long)q * D_ + c8 * 8];
        asm volatile("st.shared.v4.b32 [%0], {%1,%2,%3,%4};" ::
            "r"(qsB + q * RB + c8 * 16),
            "r"(__float_as_uint(v.x)), "r"(__float_as_uint(v.y)),
            "r"(__float_as_uint(v.z)), "r"(__float_as_uint(v.w)) : "memory");
    }
    {
        const __nv_bfloat16* Kp = K + (long)(b * S_) * D_ + h * DH_;
        const __nv_bfloat16* Vp = V + (long)(b * S_) * D_ + h * DH_;
        #pragma unroll
        for (int l = 0; l < 4; l++) {
            CP16(ksB + cKp[l] * RB + cC[l] * 16, Kp + (long)cKp[l] * D_ + cC[l] * 8);
            CP16(vnB + cKp[l] * RB + cC[l] * 16, Vp + (long)cKp[l] * D_ + cC[l] * 8);
        }
        CP_COMMIT();
    }

    float o[8][4];
    #pragma unroll
    for (int nt = 0; nt < 8; nt++)
        #pragma unroll
        for (int j = 0; j < 4; j++) o[nt][j] = 0.f;
    float m0 = -1e30f, m1 = -1e30f, l0 = 0.f, l1 = 0.f;

    const uint32_t kFragOff = ((lane & 7) + ((lane >> 4) << 3)) * RB + ((lane >> 3) & 1) * 16;
    const uint32_t vFragOff = ((lane & 7) + ((lane >> 3) & 1) * 8) * RB + (lane >> 4) * 16;

    bool qfLoaded = false;
    uint32_t qf[4][4];

    const float SC = 0.125f * 1.44269504f;   // scale * log2(e)

    int ktmax = qi + 1;
    for (int kt = 0; kt < ktmax; kt++) {
        int slot = kt % 3;
        bool havenext = (kt + 1) < ktmax;

        if (havenext) {
            int ns = (kt + 1) % 3;
            const __nv_bfloat16* Kp = K + (long)(b * S_ + (kt + 1) * 64) * D_ + h * DH_;
            const __nv_bfloat16* Vp = V + (long)(b * S_ + (kt + 1) * 64) * D_ + h * DH_;
            uint32_t kd = ksB + ns * KSLOT_B, vd = vnB + ns * KSLOT_B;
            #pragma unroll
            for (int l = 0; l < 4; l++) {
                CP16(kd + cKp[l] * RB + cC[l] * 16, Kp + (long)cKp[l] * D_ + cC[l] * 8);
                CP16(vd + cKp[l] * RB + cC[l] * 16, Vp + (long)cKp[l] * D_ + cC[l] * 8);
            }
            CP_COMMIT();
            CP_WAIT(1);
        } else {
            CP_WAIT(0);
        }
        __syncthreads();

        if (!qfLoaded) {
            uint32_t base = qsB + (w * 16 + (lane & 15)) * RB + (lane >> 4) * 16;
            #pragma unroll
            for (int ds = 0; ds < 4; ds++)
                LDSM4(qf[ds][0], qf[ds][1], qf[ds][2], qf[ds][3], base + ds * 32);
            qfLoaded = true;
        }

        {
            const uint32_t kBase = ksB + slot * KSLOT_B + kFragOff;
            const uint32_t vBase = vnB + slot * KSLOT_B + vFragOff;

            // ---- S = Q K^T ----
            float s[8][4];
            #pragma unroll
            for (int nt = 0; nt < 8; nt++)
                #pragma unroll
                for (int j = 0; j < 4; j++) s[nt][j] = 0.f;

            #pragma unroll
            for (int ds = 0; ds < 4; ds++) {
                uint32_t bf[8][2];
                #pragma unroll
                for (int ntp = 0; ntp < 4; ntp++) {
                    uint32_t r0, r1, r2, r3;
                    LDSM4(r0, r1, r2, r3, kBase + ntp * 16 * RB + ds * 32);
                    bf[2 * ntp][0] = r0; bf[2 * ntp][1] = r1;
                    bf[2 * ntp + 1][0] = r2; bf[2 * ntp + 1][1] = r3;
                }
                #pragma unroll
                for (int nt = 0; nt < 8; nt++)
                    MMA_BF16(s[nt], qf[ds], bf[nt][0], bf[nt][1]);
            }

            // ---- scale + causal mask + online softmax ----
            bool needmask = (kt * 64 + 63) > (qi * 64 + w * 16);
            int row0 = qi * 64 + w * 16 + (lane >> 2);
            float ml0 = -1e30f, ml1 = -1e30f;
            #pragma unroll
            for (int nt = 0; nt < 8; nt++) {
                #pragma unroll
                for (int j = 0; j < 4; j++) {
                    float v = s[nt][j] * SC;
                    if (needmask) {
                        int col = kt * 64 + nt * 8 + 2 * (lane & 3) + (j & 1);
                        int row = row0 + ((j >> 1) << 3);
                        if (col > row) v = -1e30f;
                    }
                    s[nt][j] = v;
                }
                ml0 = fmaxf(ml0, fmaxf(s[nt][0], s[nt][1]));
                ml1 = fmaxf(ml1, fmaxf(s[nt][2], s[nt][3]));
            }
            ml0 = fmaxf(ml0, __shfl_xor_sync(FULLMASK, ml0, 1));
            ml0 = fmaxf(ml0, __shfl_xor_sync(FULLMASK, ml0, 2));
            ml1 = fmaxf(ml1, __shfl_xor_sync(FULLMASK, ml1, 1));
            ml1 = fmaxf(ml1, __shfl_xor_sync(FULLMASK, ml1, 2));
            float mn0 = fmaxf(m0, ml0), mn1 = fmaxf(m1, ml1);
            float a0 = exp2f(m0 - mn0), a1 = exp2f(m1 - mn1);
            float sum0 = 0.f, sum1 = 0.f;
            #pragma unroll
            for (int nt = 0; nt < 8; nt++) {
                s[nt][0] = rt_bf16(exp2f(s[nt][0] - mn0));
                s[nt][1] = rt_bf16(exp2f(s[nt][1] - mn0));
                s[nt][2] = rt_bf16(exp2f(s[nt][2] - mn1));
                s[nt][3] = rt_bf16(exp2f(s[nt][3] - mn1));
                sum0 += s[nt][0] + s[nt][1];
                sum1 += s[nt][2] + s[nt][3];
            }
            sum0 += __shfl_xor_sync(FULLMASK, sum0, 1);
            sum0 += __shfl_xor_sync(FULLMASK, sum0, 2);
            sum1 += __shfl_xor_sync(FULLMASK, sum1, 1);
            sum1 += __shfl_xor_sync(FULLMASK, sum1, 2);
            l0 = l0 * a0 + sum0;
            l1 = l1 * a1 + sum1;
            m0 = mn0; m1 = mn1;
            #pragma unroll
            for (int nt = 0; nt < 8; nt++) {
                o[nt][0] *= a0; o[nt][1] *= a0;
                o[nt][2] *= a1; o[nt][3] *= a1;
            }

            // ---- O += P V : P A-fragments built directly from S C-fragments ----
            #pragma unroll
            for (int ks = 0; ks < 4; ks++) {
                uint32_t pf[4];
                pf[0] = pk_bf16x2(s[2*ks][0],   s[2*ks][1]);
                pf[1] = pk_bf16x2(s[2*ks][2],   s[2*ks][3]);
                pf[2] = pk_bf16x2(s[2*ks+1][0], s[2*ks+1][1]);
                pf[3] = pk_bf16x2(s[2*ks+1][2], s[2*ks+1][3]);
                uint32_t vf[8][2];
                #pragma unroll
                for (int ntp = 0; ntp < 4; ntp++) {
                    uint32_t r0, r1, r2, r3;
                    LDSM4T(r0, r1, r2, r3, vBase + ks * 16 * RB + ntp * 32);
                    vf[2 * ntp][0] = r0; vf[2 * ntp][1] = r1;
                    vf[2 * ntp + 1][0] = r2; vf[2 * ntp + 1][1] = r3;
                }
                #pragma unroll
                for (int nt = 0; nt < 8; nt++)
                    MMA_BF16(o[nt], pf, vf[nt][0], vf[nt][1]);
            }
        }
    }

    // normalize + write bf16
    float inv0 = 1.f / l0, inv1 = 1.f / l1;
    int row0 = qi * 64 + w * 16 + (lane >> 2);
    long base0 = (long)(b * S_ + row0) * D_ + h * DH_ + 2 * (lane & 3);
    long base1 = base0 + 8 * D_;
    #pragma unroll
    for (int nt = 0; nt < 8; nt++) {
        *(uint32_t*)&O16[base0 + nt * 8] = pk_bf16x2(o[nt][0] * inv0, o[nt][1] * inv0);
        *(uint32_t*)&O16[base1 + nt * 8] = pk_bf16x2(o[nt][2] * inv1, o[nt][3] * inv1);
    }
}

// ---------------------------------------------------------------------------
// Launch
// ---------------------------------------------------------------------------
extern "C" void kernel_launch(void* const* d_in, const int* in_sizes, int n_in,
                              void* d_out, int out_size)
{
    const float* hidden = (const float*)d_in[0];
    // d_in[1] = attention_mask: causal tril -> handled analytically
    const float* lora   = (const float*)d_in[2];   // [4, B, D, R]
    const float* ln_w   = (const float*)d_in[3];
    const float* Wq     = (const float*)d_in[4];
    const float* Wk     = (const float*)d_in[5];
    const float* Wv     = (const float*)d_in[6];
    const float* Wo     = (const float*)d_in[7];
    float* out = (float*)d_out;

    float *hq, *hk, *z;
    __nv_bfloat16 *x16, *q16, *k16, *v16, *attn16, *wq16, *wk16, *wv16, *wo16;
    cudaGetSymbolAddress((void**)&x16,    g_x16);
    cudaGetSymbolAddress((void**)&hq,     g_hq);
    cudaGetSymbolAddress((void**)&hk,     g_hk);
    cudaGetSymbolAddress((void**)&z,      g_z);
    cudaGetSymbolAddress((void**)&q16,    g_q16);
    cudaGetSymbolAddress((void**)&k16,    g_k16);
    cudaGetSymbolAddress((void**)&v16,    g_v16);
    cudaGetSymbolAddress((void**)&attn16, g_attn16);
    cudaGetSymbolAddress((void**)&wq16,   g_wq16);
    cudaGetSymbolAddress((void**)&wk16,   g_wk16);
    cudaGetSymbolAddress((void**)&wv16,   g_wv16);
    cudaGetSymbolAddress((void**)&wo16,   g_wo16);

    cudaFuncSetAttribute(gemm_qkv_kernel, cudaFuncAttributeMaxDynamicSharedMemorySize, GEMM_SMEM);
    cudaFuncSetAttribute(gemm_o_kernel,   cudaFuncAttributeMaxDynamicSharedMemorySize, GEMM_SMEM);
    cudaFuncSetAttribute(flash_mma_kernel, cudaFuncAttributeMaxDynamicSharedMemorySize, FLASH_SMEM);

    // 0+1. RMSNorm (-> bf16) + weight conversion
    prep_kernel<<<M_ + 2048, 256>>>(hidden, ln_w, Wq, Wk, Wv, Wo,
                                    x16, wq16, wk16, wv16, wo16);

    // 2. Fused QKV projections (q/k out fp32 for LoRA, V out bf16)
    dim3 gq(24, M_ / 128);
    gemm_qkv_kernel<<<gq, 256, GEMM_SMEM>>>(x16, wq16, wk16, wv16, hq, hk, v16);

    // 3. LoRA: z = h@A, then h += 2 z@B^T -> bf16
    dim3 gl(M_ / 32, 2);
    lora_z_kernel<<<gl, 256>>>(hq, hk, lora, z);
    dim3 gla(M_ / LAR, 2);
    lora_apply_kernel<<<gla, 256>>>(hq, hk, q16, k16, lora, z);

    // 4. Causal flash attention (bf16 in/out, Q-tile 64, 128 threads, reg-P)
    dim3 fg(S_ / 64, H_, B_);
    flash_mma_kernel<<<fg, 128, FLASH_SMEM>>>(q16, k16, v16, attn16);

    // 5. Output projection + residual (bf16 in, fp32 out)
    dim3 go(8, M_ / 128);
    gemm_o_kernel<<<go, 256, GEMM_SMEM>>>(attn16, wo16, hidden, out);
}

// round 16
// speedup vs baseline: 1.0865x; 1.0182x over previous
#include <cuda_runtime.h>
#include <cuda_bf16.h>
#include <cstdint>
#include <math.h>
#include <type_traits>

// Problem constants
#define B_  2
#define S_  2048
#define D_  1024
#define H_  16
#define DH_ 64
#define R_  8
#define M_  (B_*S_)          // 4096 rows

// Scratch (device globals; no allocation allowed)
__device__ __nv_bfloat16 g_x16[M_*D_];
__device__ float g_hq[M_*D_];
__device__ float g_hk[M_*D_];
__device__ float g_z[2*M_*R_];
__device__ __nv_bfloat16 g_q16[M_*D_];
__device__ __nv_bfloat16 g_k16[M_*D_];
__device__ __nv_bfloat16 g_v16[M_*D_];
__device__ __nv_bfloat16 g_attn16[M_*D_];
__device__ __nv_bfloat16 g_wq16[D_*D_];
__device__ __nv_bfloat16 g_wk16[D_*D_];
__device__ __nv_bfloat16 g_wv16[D_*D_];
__device__ __nv_bfloat16 g_wo16[D_*D_];

#define FULLMASK 0xffffffffu

// ===========================================================================
// PTX helpers
// ===========================================================================
__device__ __forceinline__ uint32_t smem_u32(const void* p) {
    uint32_t a;
    asm("{ .reg .u64 t; cvta.to.shared.u64 t, %1; cvt.u32.u64 %0, t; }"
        : "=r"(a) : "l"(p));
    return a;
}

#define LDSM4(R0,R1,R2,R3,ADDR) \
    asm volatile("ldmatrix.sync.aligned.m8n8.x4.shared.b16 {%0,%1,%2,%3}, [%4];" \
        : "=r"(R0), "=r"(R1), "=r"(R2), "=r"(R3) : "r"(ADDR))

#define LDSM4T(R0,R1,R2,R3,ADDR) \
    asm volatile("ldmatrix.sync.aligned.m8n8.x4.trans.shared.b16 {%0,%1,%2,%3}, [%4];" \
        : "=r"(R0), "=r"(R1), "=r"(R2), "=r"(R3) : "r"(ADDR))

#define MMA_BF16(C, A, B0, B1) \
    asm volatile("mma.sync.aligned.m16n8k16.row.col.f32.bf16.bf16.f32 " \
        "{%0,%1,%2,%3}, {%4,%5,%6,%7}, {%8,%9}, {%0,%1,%2,%3};" \
        : "+f"((C)[0]), "+f"((C)[1]), "+f"((C)[2]), "+f"((C)[3]) \
        : "r"((A)[0]), "r"((A)[1]), "r"((A)[2]), "r"((A)[3]), "r"(B0), "r"(B1))

#define CP16(DST, SRC) \
    asm volatile("cp.async.cg.shared.global [%0], [%1], 16;" :: "r"(DST), "l"(SRC))
#define CP_COMMIT() asm volatile("cp.async.commit_group;" ::: "memory")
#define CP_WAIT(N)  asm volatile("cp.async.wait_group %0;" :: "n"(N) : "memory")

__device__ __forceinline__ uint32_t pk_bf16x2(float a, float b) {
    __nv_bfloat162 t = __floats2bfloat162_rn(a, b);
    return *reinterpret_cast<uint32_t*>(&t);
}
__device__ __forceinline__ float rt_bf16(float a) {
    return __bfloat162float(__float2bfloat16(a));
}

// ---------------------------------------------------------------------------
// Prep: RMSNorm (blocks 0..M_-1) + weight conversion (blocks M_..M_+2047)
// ---------------------------------------------------------------------------
__global__ __launch_bounds__(256) void prep_kernel(
    const float* __restrict__ hs, const float* __restrict__ w,
    const float* __restrict__ Wq, const float* __restrict__ Wk,
    const float* __restrict__ Wv, const float* __restrict__ Wo,
    __nv_bfloat16* __restrict__ x16,
    __nv_bfloat16* __restrict__ wq16, __nv_bfloat16* __restrict__ wk16,
    __nv_bfloat16* __restrict__ wv16, __nv_bfloat16* __restrict__ wo16)
{
    int t = threadIdx.x;
    if (blockIdx.x < M_) {
        int row = blockIdx.x;
        const float* x = hs + (long)row * D_;
        float4 v = *(const float4*)&x[t * 4];
        float ss = v.x*v.x + v.y*v.y + v.z*v.z + v.w*v.w;
        #pragma unroll
        for (int o = 16; o > 0; o >>= 1) ss += __shfl_xor_sync(FULLMASK, ss, o);
        __shared__ float red[8];
        if ((t & 31) == 0) red[t >> 5] = ss;
        __syncthreads();
        __shared__ float s_inv;
        if (t == 0) {
            float s = 0.f;
            #pragma unroll
            for (int i = 0; i < 8; i++) s += red[i];
            s_inv = rsqrtf(s / (float)D_ + 1e-5f);
        }
        __syncthreads();
        float inv = s_inv;
        float4 wv4 = *(const float4*)&w[t * 4];
        uint2 o2;
        o2.x = pk_bf16x2(v.x * inv * wv4.x, v.y * inv * wv4.y);
        o2.y = pk_bf16x2(v.z * inv * wv4.z, v.w * inv * wv4.w);
        *(uint2*)&x16[(long)row * D_ + t * 4] = o2;
    } else {
        int bid2 = blockIdx.x - M_;
        int sel = bid2 >> 9;
        int ib  = bid2 & 511;
        const float* src = (sel == 0) ? Wq : (sel == 1) ? Wk : (sel == 2) ? Wv : Wo;
        __nv_bfloat16* dst = (sel == 0) ? wq16 : (sel == 1) ? wk16 : (sel == 2) ? wv16 : wo16;
        long idx = ((long)ib * 256 + t) * 8;
        float4 a = *(const float4*)&src[idx];
        float4 b = *(const float4*)&src[idx + 4];
        uint4 u;
        u.x = pk_bf16x2(a.x, a.y); u.y = pk_bf16x2(a.z, a.w);
        u.z = pk_bf16x2(b.x, b.y); u.w = pk_bf16x2(b.z, b.w);
        *(uint4*)&dst[idx] = u;
    }
}

// ---------------------------------------------------------------------------
// bf16 GEMM core: C[128x128] = A[*,1024] @ W[*,1024]^T.
// BK=64 bf16, 3-slot cp.async ring, ONE barrier per k-chunk.
// 8 warps x (32x64). MODE: 0 = fp32 out, 1 = fp32 + residual, 2 = bf16 out
// ---------------------------------------------------------------------------
#define RBW 144                     // 64 bf16 = 128B data + 16B pad
#define WTILE_B (128*RBW)           // 18432
#define GEMM_SMEM (6*WTILE_B)       // 110592 (3 slots A + 3 slots B)

template <int MODE>
__device__ __forceinline__ void gemm128_bf16_core(
    const __nv_bfloat16* __restrict__ A, const __nv_bfloat16* __restrict__ W,
    const float* __restrict__ resid, float* __restrict__ C32,
    __nv_bfloat16* __restrict__ C16,
    int by, int bx, char* gsm)
{
    const uint32_t sA = smem_u32(gsm);
    const uint32_t sB = sA + 3 * WTILE_B;
    int tid = threadIdx.x;
    int lane = tid & 31;
    int w = tid >> 5;
    int wm = (w >> 1) * 32;
    int wn = (w & 1) * 64;

    const __nv_bfloat16* aP[4]; const __nv_bfloat16* bP[4];
    uint32_t stA[4], stB[4];
    #pragma unroll
    for (int l = 0; l < 4; l++) {
        int idx = tid + l * 256;
        int r = idx >> 3, c8 = idx & 7;
        aP[l] = A + (long)(by * 128 + r) * D_ + c8 * 8;
        bP[l] = W + (long)(bx * 128 + r) * D_ + c8 * 8;
        stA[l] = sA + r * RBW + c8 * 16;
        stB[l] = sB + r * RBW + c8 * 16;
    }

    float acc[2][8][4];
    #pragma unroll
    for (int mt = 0; mt < 2; mt++)
        #pragma unroll
        for (int nt = 0; nt < 8; nt++)
            #pragma unroll
            for (int j = 0; j < 4; j++) acc[mt][nt][j] = 0.f;

    const uint32_t aFragBase = sA + (wm + (lane & 15)) * RBW + (lane >> 4) * 16;
    const uint32_t bFragBase = sB +
        (wn + (lane & 7) + ((lane >> 4) << 3)) * RBW + ((lane >> 3) & 1) * 16;

    // Prologue: stage chunks 0 and 1
    #pragma unroll
    for (int l = 0; l < 4; l++) { CP16(stA[l], aP[l]); CP16(stB[l], bP[l]); }
    CP_COMMIT();
    #pragma unroll
    for (int l = 0; l < 4; l++) {
        CP16(stA[l] + WTILE_B, aP[l] + 64);
        CP16(stB[l] + WTILE_B, bP[l] + 64);
    }
    CP_COMMIT();

    for (int kc = 0; kc < 16; kc++) {          // D/64
        if (kc < 15) { CP_WAIT(1); } else { CP_WAIT(0); }
        __syncthreads();

        if (kc + 2 < 16) {
            int ns = (kc + 2) % 3;
            #pragma unroll
            for (int l = 0; l < 4; l++) {
                CP16(stA[l] + ns * WTILE_B, aP[l] + (kc + 2) * 64);
                CP16(stB[l] + ns * WTILE_B, bP[l] + (kc + 2) * 64);
            }
            CP_COMMIT();
        }

        int slot = kc % 3;
        uint32_t aBuf = aFragBase + slot * WTILE_B;
        uint32_t bBuf = bFragBase + slot * WTILE_B;

        #pragma unroll
        for (int ks = 0; ks < 4; ks++) {
            uint32_t af[2][4];
            uint32_t bf[8][2];
            #pragma unroll
            for (int mt = 0; mt < 2; mt++)
                LDSM4(af[mt][0], af[mt][1], af[mt][2], af[mt][3],
                      aBuf + mt * 16 * RBW + ks * 32);
            #pragma unroll
            for (int ntp = 0; ntp < 4; ntp++) {
                uint32_t r0, r1, r2, r3;
                LDSM4(r0, r1, r2, r3, bBuf + ntp * 16 * RBW + ks * 32);
                bf[2 * ntp][0] = r0; bf[2 * ntp][1] = r1;
                bf[2 * ntp + 1][0] = r2; bf[2 * ntp + 1][1] = r3;
            }
            #pragma unroll
            for (int mt = 0; mt < 2; mt++)
                #pragma unroll
                for (int nt = 0; nt < 8; nt++)
                    MMA_BF16(acc[mt][nt], af[mt], bf[nt][0], bf[nt][1]);
        }
    }

    #pragma unroll
    for (int mt = 0; mt < 2; mt++) {
        int row = by * 128 + wm + mt * 16 + (lane >> 2);
        int col = bx * 128 + wn + 2 * (lane & 3);
        #pragma unroll
        for (int nt = 0; nt < 8; nt++) {
            long i0 = (long)row * D_ + col + nt * 8;
            long i1 = i0 + 8 * D_;
            if (MODE == 2) {
                *(uint32_t*)&C16[i0] = pk_bf16x2(acc[mt][nt][0], acc[mt][nt][1]);
                *(uint32_t*)&C16[i1] = pk_bf16x2(acc[mt][nt][2], acc[mt][nt][3]);
            } else {
                float2 v0 = make_float2(acc[mt][nt][0], acc[mt][nt][1]);
                float2 v1 = make_float2(acc[mt][nt][2], acc[mt][nt][3]);
                if (MODE == 1) {
                    float2 r0 = *(const float2*)&resid[i0];
                    float2 r1 = *(const float2*)&resid[i1];
                    v0.x += r0.x; v0.y += r0.y;
                    v1.x += r1.x; v1.y += r1.y;
                }
                *(float2*)&C32[i0] = v0;
                *(float2*)&C32[i1] = v1;
            }
        }
    }
}

__global__ __launch_bounds__(256, 2) void gemm_qkv_kernel(
    const __nv_bfloat16* __restrict__ A,
    const __nv_bfloat16* __restrict__ Wq, const __nv_bfloat16* __restrict__ Wk,
    const __nv_bfloat16* __restrict__ Wv,
    float* __restrict__ hq, float* __restrict__ hk, __nv_bfloat16* __restrict__ v16)
{
    extern __shared__ __align__(16) char gsm[];
    int wsel = blockIdx.x >> 3;
    int bx = blockIdx.x & 7;
    if (wsel == 0)
        gemm128_bf16_core<0>(A, Wq, nullptr, hq, nullptr, blockIdx.y, bx, gsm);
    else if (wsel == 1)
        gemm128_bf16_core<0>(A, Wk, nullptr, hk, nullptr, blockIdx.y, bx, gsm);
    else
        gemm128_bf16_core<2>(A, Wv, nullptr, nullptr, v16, blockIdx.y, bx, gsm);
}

__global__ __launch_bounds__(256, 2) void gemm_o_kernel(
    const __nv_bfloat16* __restrict__ A, const __nv_bfloat16* __restrict__ W,
    const float* __restrict__ resid, float* __restrict__ C)
{
    extern __shared__ __align__(16) char gsm[];
    gemm128_bf16_core<1>(A, W, resid, C, nullptr, blockIdx.y, blockIdx.x, gsm);
}

// ---------------------------------------------------------------------------
// LoRA phase 1: z[row][:] = h[row] @ A   (grid: (M_/32, 2), 256 threads)
// ---------------------------------------------------------------------------
__global__ __launch_bounds__(256) void lora_z_kernel(
    const float* __restrict__ hq, const float* __restrict__ hk,
    const float* __restrict__ lora, float* __restrict__ z)
{
    int which = blockIdx.y;
    const float* h = which ? hk : hq;
    int rowBase = blockIdx.x * 32;
    int b = rowBase / S_;
    const float* Ag = lora + ((long)which * B_ + b) * D_ * R_;

    __shared__ float As[R_ * D_];
    int tid = threadIdx.x;
    int lane = tid & 31, w = tid >> 5;

    #pragma unroll
    for (int k = 0; k < 4; k++) {
        int d = tid + k * 256;
        float4 a0 = *(const float4*)&Ag[d * R_];
        float4 a1 = *(const float4*)&Ag[d * R_ + 4];
        As[0*D_+d] = a0.x; As[1*D_+d] = a0.y; As[2*D_+d] = a0.z; As[3*D_+d] = a0.w;
        As[4*D_+d] = a1.x; As[5*D_+d] = a1.y; As[6*D_+d] = a1.z; As[7*D_+d] = a1.w;
    }
    __syncthreads();

    #pragma unroll
    for (int rr = 0; rr < 4; rr++) {
        int row = rowBase + w * 4 + rr;
        const float* hrow = h + (long)row * D_;
        float part[R_];
        #pragma unroll
        for (int r = 0; r < R_; r++) part[r] = 0.f;
        #pragma unroll
        for (int k = 0; k < 32; k++) {
            int d = lane + k * 32;
            float hv = hrow[d];
            #pragma unroll
            for (int r = 0; r < R_; r++) part[r] += hv * As[r * D_ + d];
        }
        #pragma unroll
        for (int r = 0; r < R_; r++)
            #pragma unroll
            for (int o = 16; o > 0; o >>= 1)
                part[r] += __shfl_xor_sync(FULLMASK, part[r], o);
        if (lane == 0) {
            #pragma unroll
            for (int r = 0; r < R_; r++)
                z[((long)which * M_ + row) * R_ + r] = part[r];
        }
    }
}

// ---------------------------------------------------------------------------
// LoRA phase 2: g16 = bf16(h + 2*z@B^T). Grid (M_/16, 2), 256 threads.
// ---------------------------------------------------------------------------
#define LAR 16
__global__ __launch_bounds__(256) void lora_apply_kernel(
    const float* __restrict__ hq, const float* __restrict__ hk,
    __nv_bfloat16* __restrict__ q16, __nv_bfloat16* __restrict__ k16,
    const float* __restrict__ lora, const float* __restrict__ z)
{
    int which = blockIdx.y;
    const float* h = which ? hk : hq;
    __nv_bfloat16* g16 = which ? k16 : q16;
    int rowBase = blockIdx.x * LAR;
    int b = rowBase / S_;
    const float* Bg = lora + ((long)(2 + which) * B_ + b) * D_ * R_;

    __shared__ float zs[LAR][R_];
    int tid = threadIdx.x;
    if (tid < LAR * R_)
        zs[tid >> 3][tid & 7] = z[((long)which * M_ + rowBase + (tid >> 3)) * R_ + (tid & 7)];
    __syncthreads();

    int d0 = tid * 4;
    float br[4][R_];
    #pragma unroll
    for (int j = 0; j < 4; j++) {
        float4 b0 = *(const float4*)&Bg[(d0 + j) * R_];
        float4 b1 = *(const float4*)&Bg[(d0 + j) * R_ + 4];
        br[j][0] = b0.x; br[j][1] = b0.y; br[j][2] = b0.z; br[j][3] = b0.w;
        br[j][4] = b1.x; br[j][5] = b1.y; br[j][6] = b1.z; br[j][7] = b1.w;
    }

    #pragma unroll 4
    for (int rr = 0; rr < LAR; rr++) {
        long idx = (long)(rowBase + rr) * D_ + d0;
        float4 hv = *(const float4*)&h[idx];
        float del[4];
        #pragma unroll
        for (int j = 0; j < 4; j++) {
            float s = 0.f;
            #pragma unroll
            for (int r = 0; r < R_; r++) s += zs[rr][r] * br[j][r];
            del[j] = s;
        }
        uint2 o2;
        o2.x = pk_bf16x2(hv.x + 2.f * del[0], hv.y + 2.f * del[1]);
        o2.y = pk_bf16x2(hv.z + 2.f * del[2], hv.w + 2.f * del[3]);
        *(uint2*)&g16[idx] = o2;
    }
}

// ---------------------------------------------------------------------------
// Flash attention, bf16 mma, causal. Q tile 64, K/V tile 64, 128 threads,
// 3 CTAs/SM. P in registers. Mainloop specialized: mask only on diag tile.
// ---------------------------------------------------------------------------
#define RB 144
#define KSLOT_B (64 * RB)
#define FQ_B  (64 * RB)
#define FLASH_SMEM (FQ_B + 3*KSLOT_B + 3*KSLOT_B)   // 64512

__global__ __launch_bounds__(128, 3) void flash_mma_kernel(
    const __nv_bfloat16* __restrict__ Q, const __nv_bfloat16* __restrict__ K,
    const __nv_bfloat16* __restrict__ V, __nv_bfloat16* __restrict__ O16)
{
    extern __shared__ __align__(16) char smc[];
    const uint32_t qsB = smem_u32(smc);
    const uint32_t ksB = qsB + FQ_B;
    const uint32_t vnB = ksB + 3 * KSLOT_B;

    int qi = (gridDim.x - 1) - blockIdx.x;   // heavy tiles first
    int h  = blockIdx.y;
    int b  = blockIdx.z;
    int tid = threadIdx.x;
    int lane = tid & 31;
    int w = tid >> 5;

    int cKp[4], cC[4];
    #pragma unroll
    for (int l = 0; l < 4; l++) {
        int idx = tid + l * 128;
        cKp[l] = idx >> 3; cC[l] = idx & 7;
    }

    const __nv_bfloat16* Qp = Q + (long)(b * S_ + qi * 64) * D_ + h * DH_;
    #pragma unroll
    for (int l = 0; l < 4; l++) {
        int idx = tid + l * 128;
        int q = idx >> 3, c8 = idx & 7;
        float4 v = *(const float4*)&Qp[(long)q * D_ + c8 * 8];
        asm volatile("st.shared.v4.b32 [%0], {%1,%2,%3,%4};" ::
            "r"(qsB + q * RB + c8 * 16),
            "r"(__float_as_uint(v.x)), "r"(__float_as_uint(v.y)),
            "r"(__float_as_uint(v.z)), "r"(__float_as_uint(v.w)) : "memory");
    }
    {
        const __nv_bfloat16* Kp = K + (long)(b * S_) * D_ + h * DH_;
        const __nv_bfloat16* Vp = V + (long)(b * S_) * D_ + h * DH_;
        #pragma unroll
        for (int l = 0; l < 4; l++) {
            CP16(ksB + cKp[l] * RB + cC[l] * 16, Kp + (long)cKp[l] * D_ + cC[l] * 8);
            CP16(vnB + cKp[l] * RB + cC[l] * 16, Vp + (long)cKp[l] * D_ + cC[l] * 8);
        }
        CP_COMMIT();
    }

    float o[8][4];
    #pragma unroll
    for (int nt = 0; nt < 8; nt++)
        #pragma unroll
        for (int j = 0; j < 4; j++) o[nt][j] = 0.f;
    float m0 = -1e30f, m1 = -1e30f, l0 = 0.f, l1 = 0.f;

    const uint32_t kFragOff = ((lane & 7) + ((lane >> 4) << 3)) * RB + ((lane >> 3) & 1) * 16;
    const uint32_t vFragOff = ((lane & 7) + ((lane >> 3) & 1) * 8) * RB + (lane >> 4) * 16;

    bool qfLoaded = false;
    uint32_t qf[4][4];

    const float SC = 0.125f * 1.44269504f;   // scale * log2(e)
    int ktmax = qi + 1;

    // Tile body; MASK is a compile-time bool via integral_constant.
    auto tile_body = [&](int kt, auto maskc) {
        constexpr bool MASK = decltype(maskc)::value;
        int slot = kt % 3;
        bool havenext = (kt + 1) < ktmax;

        if (havenext) {
            int ns = (kt + 1) % 3;
            const __nv_bfloat16* Kp = K + (long)(b * S_ + (kt + 1) * 64) * D_ + h * DH_;
            const __nv_bfloat16* Vp = V + (long)(b * S_ + (kt + 1) * 64) * D_ + h * DH_;
            uint32_t kd = ksB + ns * KSLOT_B, vd = vnB + ns * KSLOT_B;
            #pragma unroll
            for (int l = 0; l < 4; l++) {
                CP16(kd + cKp[l] * RB + cC[l] * 16, Kp + (long)cKp[l] * D_ + cC[l] * 8);
                CP16(vd + cKp[l] * RB + cC[l] * 16, Vp + (long)cKp[l] * D_ + cC[l] * 8);
            }
            CP_COMMIT();
            CP_WAIT(1);
        } else {
            CP_WAIT(0);
        }
        __syncthreads();

        if (!qfLoaded) {
            uint32_t base = qsB + (w * 16 + (lane & 15)) * RB + (lane >> 4) * 16;
            #pragma unroll
            for (int ds = 0; ds < 4; ds++)
                LDSM4(qf[ds][0], qf[ds][1], qf[ds][2], qf[ds][3], base + ds * 32);
            qfLoaded = true;
        }

        const uint32_t kBase = ksB + slot * KSLOT_B + kFragOff;
        const uint32_t vBase = vnB + slot * KSLOT_B + vFragOff;

        // ---- S = Q K^T ----
        float s[8][4];
        #pragma unroll
        for (int nt = 0; nt < 8; nt++)
            #pragma unroll
            for (int j = 0; j < 4; j++) s[nt][j] = 0.f;

        #pragma unroll
        for (int ds = 0; ds < 4; ds++) {
            uint32_t bf[8][2];
            #pragma unroll
            for (int ntp = 0; ntp < 4; ntp++) {
                uint32_t r0, r1, r2, r3;
                LDSM4(r0, r1, r2, r3, kBase + ntp * 16 * RB + ds * 32);
                bf[2 * ntp][0] = r0; bf[2 * ntp][1] = r1;
                bf[2 * ntp + 1][0] = r2; bf[2 * ntp + 1][1] = r3;
            }
            #pragma unroll
            for (int nt = 0; nt < 8; nt++)
                MMA_BF16(s[nt], qf[ds], bf[nt][0], bf[nt][1]);
        }

        // ---- scale (+ causal mask only on diagonal tile) + online softmax ----
        float ml0 = -1e30f, ml1 = -1e30f;
        #pragma unroll
        for (int nt = 0; nt < 8; nt++) {
            #pragma unroll
            for (int j = 0; j < 4; j++) {
                float v = s[nt][j] * SC;
                if (MASK) {
                    int col = kt * 64 + nt * 8 + 2 * (lane & 3) + (j & 1);
                    int row = qi * 64 + w * 16 + (lane >> 2) + ((j >> 1) << 3);
                    if (col > row) v = -1e30f;
                }
                s[nt][j] = v;
            }
            ml0 = fmaxf(ml0, fmaxf(s[nt][0], s[nt][1]));
            ml1 = fmaxf(ml1, fmaxf(s[nt][2], s[nt][3]));
        }
        ml0 = fmaxf(ml0, __shfl_xor_sync(FULLMASK, ml0, 1));
        ml0 = fmaxf(ml0, __shfl_xor_sync(FULLMASK, ml0, 2));
        ml1 = fmaxf(ml1, __shfl_xor_sync(FULLMASK, ml1, 1));
        ml1 = fmaxf(ml1, __shfl_xor_sync(FULLMASK, ml1, 2));
        float mn0 = fmaxf(m0, ml0), mn1 = fmaxf(m1, ml1);
        float a0 = exp2f(m0 - mn0), a1 = exp2f(m1 - mn1);
        float sum0 = 0.f, sum1 = 0.f;
        #pragma unroll
        for (int nt = 0; nt < 8; nt++) {
            s[nt][0] = rt_bf16(exp2f(s[nt][0] - mn0));
            s[nt][1] = rt_bf16(exp2f(s[nt][1] - mn0));
            s[nt][2] = rt_bf16(exp2f(s[nt][2] - mn1));
            s[nt][3] = rt_bf16(exp2f(s[nt][3] - mn1));
            sum0 += s[nt][0] + s[nt][1];
            sum1 += s[nt][2] + s[nt][3];
        }
        sum0 += __shfl_xor_sync(FULLMASK, sum0, 1);
        sum0 += __shfl_xor_sync(FULLMASK, sum0, 2);
        sum1 += __shfl_xor_sync(FULLMASK, sum1, 1);
        sum1 += __shfl_xor_sync(FULLMASK, sum1, 2);
        l0 = l0 * a0 + sum0;
        l1 = l1 * a1 + sum1;
        m0 = mn0; m1 = mn1;
        #pragma unroll
        for (int nt = 0; nt < 8; nt++) {
            o[nt][0] *= a0; o[nt][1] *= a0;
            o[nt][2] *= a1; o[nt][3] *= a1;
        }

        // ---- O += P V : P A-frags built directly from S C-frags ----
        #pragma unroll
        for (int ks = 0; ks < 4; ks++) {
            uint32_t pf[4];
            pf[0] = pk_bf16x2(s[2*ks][0],   s[2*ks][1]);
            pf[1] = pk_bf16x2(s[2*ks][2],   s[2*ks][3]);
            pf[2] = pk_bf16x2(s[2*ks+1][0], s[2*ks+1][1]);
            pf[3] = pk_bf16x2(s[2*ks+1][2], s[2*ks+1][3]);
            uint32_t vf[8][2];
            #pragma unroll
            for (int ntp = 0; ntp < 4; ntp++) {
                uint32_t r0, r1, r2, r3;
                LDSM4T(r0, r1, r2, r3, vBase + ks * 16 * RB + ntp * 32);
                vf[2 * ntp][0] = r0; vf[2 * ntp][1] = r1;
                vf[2 * ntp + 1][0] = r2; vf[2 * ntp + 1][1] = r3;
            }
            #pragma unroll
            for (int nt = 0; nt < 8; nt++)
                MMA_BF16(o[nt], pf, vf[nt][0], vf[nt][1]);
        }
    };

    // Off-diagonal tiles: mask provably never fires (col < qi*64 <= row).
    for (int kt = 0; kt < ktmax - 1; kt++)
        tile_body(kt, std::integral_constant<bool, false>{});
    // Diagonal tile (kt == qi): masked.
    tile_body(ktmax - 1, std::integral_constant<bool, true>{});

    // normalize + write bf16
    float inv0 = 1.f / l0, inv1 = 1.f / l1;
    int row0 = qi * 64 + w * 16 + (lane >> 2);
    long base0 = (long)(b * S_ + row0) * D_ + h * DH_ + 2 * (lane & 3);
    long base1 = base0 + 8 * D_;
    #pragma unroll
    for (int nt = 0; nt < 8; nt++) {
        *(uint32_t*)&O16[base0 + nt * 8] = pk_bf16x2(o[nt][0] * inv0, o[nt][1] * inv0);
        *(uint32_t*)&O16[base1 + nt * 8] = pk_bf16x2(o[nt][2] * inv1, o[nt][3] * inv1);
    }
}

// ---------------------------------------------------------------------------
// Launch
// ---------------------------------------------------------------------------
extern "C" void kernel_launch(void* const* d_in, const int* in_sizes, int n_in,
                              void* d_out, int out_size)
{
    const float* hidden = (const float*)d_in[0];
    // d_in[1] = attention_mask: causal tril -> handled analytically
    const float* lora   = (const float*)d_in[2];   // [4, B, D, R]
    const float* ln_w   = (const float*)d_in[3];
    const float* Wq     = (const float*)d_in[4];
    const float* Wk     = (const float*)d_in[5];
    const float* Wv     = (const float*)d_in[6];
    const float* Wo     = (const float*)d_in[7];
    float* out = (float*)d_out;

    float *hq, *hk, *z;
    __nv_bfloat16 *x16, *q16, *k16, *v16, *attn16, *wq16, *wk16, *wv16, *wo16;
    cudaGetSymbolAddress((void**)&x16,    g_x16);
    cudaGetSymbolAddress((void**)&hq,     g_hq);
    cudaGetSymbolAddress((void**)&hk,     g_hk);
    cudaGetSymbolAddress((void**)&z,      g_z);
    cudaGetSymbolAddress((void**)&q16,    g_q16);
    cudaGetSymbolAddress((void**)&k16,    g_k16);
    cudaGetSymbolAddress((void**)&v16,    g_v16);
    cudaGetSymbolAddress((void**)&attn16, g_attn16);
    cudaGetSymbolAddress((void**)&wq16,   g_wq16);
    cudaGetSymbolAddress((void**)&wk16,   g_wk16);
    cudaGetSymbolAddress((void**)&wv16,   g_wv16);
    cudaGetSymbolAddress((void**)&wo16,   g_wo16);

    cudaFuncSetAttribute(gemm_qkv_kernel, cudaFuncAttributeMaxDynamicSharedMemorySize, GEMM_SMEM);
    cudaFuncSetAttribute(gemm_o_kernel,   cudaFuncAttributeMaxDynamicSharedMemorySize, GEMM_SMEM);
    cudaFuncSetAttribute(flash_mma_kernel, cudaFuncAttributeMaxDynamicSharedMemorySize, FLASH_SMEM);

    // 0+1. RMSNorm (-> bf16) + weight conversion
    prep_kernel<<<M_ + 2048, 256>>>(hidden, ln_w, Wq, Wk, Wv, Wo,
                                    x16, wq16, wk16, wv16, wo16);

    // 2. Fused QKV projections (q/k out fp32 for LoRA, V out bf16)
    dim3 gq(24, M_ / 128);
    gemm_qkv_kernel<<<gq, 256, GEMM_SMEM>>>(x16, wq16, wk16, wv16, hq, hk, v16);

    // 3. LoRA: z = h@A, then h += 2 z@B^T -> bf16
    dim3 gl(M_ / 32, 2);
    lora_z_kernel<<<gl, 256>>>(hq, hk, lora, z);
    dim3 gla(M_ / LAR, 2);
    lora_apply_kernel<<<gla, 256>>>(hq, hk, q16, k16, lora, z);

    // 4. Causal flash attention (bf16 in/out, Q-tile 64, 128 threads, reg-P)
    dim3 fg(S_ / 64, H_, B_);
    flash_mma_kernel<<<fg, 128, FLASH_SMEM>>>(q16, k16, v16, attn16);

    // 5. Output projection + residual (bf16 in, fp32 out)
    dim3 go(8, M_ / 128);
    gemm_o_kernel<<<go, 256, GEMM_SMEM>>>(attn16, wo16, hidden, out);
}

// round 17
// speedup vs baseline: 1.1224x; 1.0331x over previous
#include <cuda_runtime.h>
#include <cuda_bf16.h>
#include <cstdint>
#include <math.h>
#include <type_traits>

// Problem constants
#define B_  2
#define S_  2048
#define D_  1024
#define H_  16
#define DH_ 64
#define R_  8
#define M_  (B_*S_)          // 4096 rows

// Scratch (device globals; no allocation allowed)
__device__ __nv_bfloat16 g_x16[M_*D_];
__device__ float g_hq[M_*D_];
__device__ float g_hk[M_*D_];
__device__ float g_z[2*M_*R_];
__device__ __nv_bfloat16 g_q16[M_*D_];
__device__ __nv_bfloat16 g_k16[M_*D_];
__device__ __nv_bfloat16 g_v16[M_*D_];
__device__ __nv_bfloat16 g_attn16[M_*D_];
__device__ __nv_bfloat16 g_wq16[D_*D_];
__device__ __nv_bfloat16 g_wk16[D_*D_];
__device__ __nv_bfloat16 g_wv16[D_*D_];
__device__ __nv_bfloat16 g_wo16[D_*D_];

#define FULLMASK 0xffffffffu

// ===========================================================================
// PTX helpers
// ===========================================================================
__device__ __forceinline__ uint32_t smem_u32(const void* p) {
    uint32_t a;
    asm("{ .reg .u64 t; cvta.to.shared.u64 t, %1; cvt.u32.u64 %0, t; }"
        : "=r"(a) : "l"(p));
    return a;
}

__device__ __forceinline__ float ex2(float x) {
    float r;
    asm("ex2.approx.f32 %0, %1;" : "=f"(r) : "f"(x));
    return r;
}

#define LDSM4(R0,R1,R2,R3,ADDR) \
    asm volatile("ldmatrix.sync.aligned.m8n8.x4.shared.b16 {%0,%1,%2,%3}, [%4];" \
        : "=r"(R0), "=r"(R1), "=r"(R2), "=r"(R3) : "r"(ADDR))

#define LDSM4T(R0,R1,R2,R3,ADDR) \
    asm volatile("ldmatrix.sync.aligned.m8n8.x4.trans.shared.b16 {%0,%1,%2,%3}, [%4];" \
        : "=r"(R0), "=r"(R1), "=r"(R2), "=r"(R3) : "r"(ADDR))

#define MMA_BF16(C, A, B0, B1) \
    asm volatile("mma.sync.aligned.m16n8k16.row.col.f32.bf16.bf16.f32 " \
        "{%0,%1,%2,%3}, {%4,%5,%6,%7}, {%8,%9}, {%0,%1,%2,%3};" \
        : "+f"((C)[0]), "+f"((C)[1]), "+f"((C)[2]), "+f"((C)[3]) \
        : "r"((A)[0]), "r"((A)[1]), "r"((A)[2]), "r"((A)[3]), "r"(B0), "r"(B1))

#define CP16(DST, SRC) \
    asm volatile("cp.async.cg.shared.global [%0], [%1], 16;" :: "r"(DST), "l"(SRC))
#define CP_COMMIT() asm volatile("cp.async.commit_group;" ::: "memory")
#define CP_WAIT(N)  asm volatile("cp.async.wait_group %0;" :: "n"(N) : "memory")

__device__ __forceinline__ uint32_t pk_bf16x2(float a, float b) {
    __nv_bfloat162 t = __floats2bfloat162_rn(a, b);
    return *reinterpret_cast<uint32_t*>(&t);
}

// ---------------------------------------------------------------------------
// Prep: RMSNorm (blocks 0..M_-1) + weight conversion (blocks M_..M_+2047)
// ---------------------------------------------------------------------------
__global__ __launch_bounds__(256) void prep_kernel(
    const float* __restrict__ hs, const float* __restrict__ w,
    const float* __restrict__ Wq, const float* __restrict__ Wk,
    const float* __restrict__ Wv, const float* __restrict__ Wo,
    __nv_bfloat16* __restrict__ x16,
    __nv_bfloat16* __restrict__ wq16, __nv_bfloat16* __restrict__ wk16,
    __nv_bfloat16* __restrict__ wv16, __nv_bfloat16* __restrict__ wo16)
{
    int t = threadIdx.x;
    if (blockIdx.x < M_) {
        int row = blockIdx.x;
        const float* x = hs + (long)row * D_;
        float4 v = *(const float4*)&x[t * 4];
        float ss = v.x*v.x + v.y*v.y + v.z*v.z + v.w*v.w;
        #pragma unroll
        for (int o = 16; o > 0; o >>= 1) ss += __shfl_xor_sync(FULLMASK, ss, o);
        __shared__ float red[8];
        if ((t & 31) == 0) red[t >> 5] = ss;
        __syncthreads();
        __shared__ float s_inv;
        if (t == 0) {
            float s = 0.f;
            #pragma unroll
            for (int i = 0; i < 8; i++) s += red[i];
            s_inv = rsqrtf(s / (float)D_ + 1e-5f);
        }
        __syncthreads();
        float inv = s_inv;
        float4 wv4 = *(const float4*)&w[t * 4];
        uint2 o2;
        o2.x = pk_bf16x2(v.x * inv * wv4.x, v.y * inv * wv4.y);
        o2.y = pk_bf16x2(v.z * inv * wv4.z, v.w * inv * wv4.w);
        *(uint2*)&x16[(long)row * D_ + t * 4] = o2;
    } else {
        int bid2 = blockIdx.x - M_;
        int sel = bid2 >> 9;
        int ib  = bid2 & 511;
        const float* src = (sel == 0) ? Wq : (sel == 1) ? Wk : (sel == 2) ? Wv : Wo;
        __nv_bfloat16* dst = (sel == 0) ? wq16 : (sel == 1) ? wk16 : (sel == 2) ? wv16 : wo16;
        long idx = ((long)ib * 256 + t) * 8;
        float4 a = *(const float4*)&src[idx];
        float4 b = *(const float4*)&src[idx + 4];
        uint4 u;
        u.x = pk_bf16x2(a.x, a.y); u.y = pk_bf16x2(a.z, a.w);
        u.z = pk_bf16x2(b.x, b.y); u.w = pk_bf16x2(b.z, b.w);
        *(uint4*)&dst[idx] = u;
    }
}

// ---------------------------------------------------------------------------
// bf16 GEMM core: C[128x128] = A[*,1024] @ W[*,1024]^T.
// BK=64 bf16, 3-slot cp.async ring, ONE barrier per k-chunk.
// 8 warps x (32x64). MODE: 0 = fp32 out, 1 = fp32 + residual, 2 = bf16 out
// ---------------------------------------------------------------------------
#define RBW 144                     // 64 bf16 = 128B data + 16B pad
#define WTILE_B (128*RBW)           // 18432
#define GEMM_SMEM (6*WTILE_B)       // 110592 (3 slots A + 3 slots B)

template <int MODE>
__device__ __forceinline__ void gemm128_bf16_core(
    const __nv_bfloat16* __restrict__ A, const __nv_bfloat16* __restrict__ W,
    const float* __restrict__ resid, float* __restrict__ C32,
    __nv_bfloat16* __restrict__ C16,
    int by, int bx, char* gsm)
{
    const uint32_t sA = smem_u32(gsm);
    const uint32_t sB = sA + 3 * WTILE_B;
    int tid = threadIdx.x;
    int lane = tid & 31;
    int w = tid >> 5;
    int wm = (w >> 1) * 32;
    int wn = (w & 1) * 64;

    const __nv_bfloat16* aP[4]; const __nv_bfloat16* bP[4];
    uint32_t stA[4], stB[4];
    #pragma unroll
    for (int l = 0; l < 4; l++) {
        int idx = tid + l * 256;
        int r = idx >> 3, c8 = idx & 7;
        aP[l] = A + (long)(by * 128 + r) * D_ + c8 * 8;
        bP[l] = W + (long)(bx * 128 + r) * D_ + c8 * 8;
        stA[l] = sA + r * RBW + c8 * 16;
        stB[l] = sB + r * RBW + c8 * 16;
    }

    float acc[2][8][4];
    #pragma unroll
    for (int mt = 0; mt < 2; mt++)
        #pragma unroll
        for (int nt = 0; nt < 8; nt++)
            #pragma unroll
            for (int j = 0; j < 4; j++) acc[mt][nt][j] = 0.f;

    const uint32_t aFragBase = sA + (wm + (lane & 15)) * RBW + (lane >> 4) * 16;
    const uint32_t bFragBase = sB +
        (wn + (lane & 7) + ((lane >> 4) << 3)) * RBW + ((lane >> 3) & 1) * 16;

    // Prologue: stage chunks 0 and 1
    #pragma unroll
    for (int l = 0; l < 4; l++) { CP16(stA[l], aP[l]); CP16(stB[l], bP[l]); }
    CP_COMMIT();
    #pragma unroll
    for (int l = 0; l < 4; l++) {
        CP16(stA[l] + WTILE_B, aP[l] + 64);
        CP16(stB[l] + WTILE_B, bP[l] + 64);
    }
    CP_COMMIT();

    for (int kc = 0; kc < 16; kc++) {          // D/64
        if (kc < 15) { CP_WAIT(1); } else { CP_WAIT(0); }
        __syncthreads();

        if (kc + 2 < 16) {
            int ns = (kc + 2) % 3;
            #pragma unroll
            for (int l = 0; l < 4; l++) {
                CP16(stA[l] + ns * WTILE_B, aP[l] + (kc + 2) * 64);
                CP16(stB[l] + ns * WTILE_B, bP[l] + (kc + 2) * 64);
            }
            CP_COMMIT();
        }

        int slot = kc % 3;
        uint32_t aBuf = aFragBase + slot * WTILE_B;
        uint32_t bBuf = bFragBase + slot * WTILE_B;

        #pragma unroll
        for (int ks = 0; ks < 4; ks++) {
            uint32_t af[2][4];
            uint32_t bf[8][2];
            #pragma unroll
            for (int mt = 0; mt < 2; mt++)
                LDSM4(af[mt][0], af[mt][1], af[mt][2], af[mt][3],
                      aBuf + mt * 16 * RBW + ks * 32);
            #pragma unroll
            for (int ntp = 0; ntp < 4; ntp++) {
                uint32_t r0, r1, r2, r3;
                LDSM4(r0, r1, r2, r3, bBuf + ntp * 16 * RBW + ks * 32);
                bf[2 * ntp][0] = r0; bf[2 * ntp][1] = r1;
                bf[2 * ntp + 1][0] = r2; bf[2 * ntp + 1][1] = r3;
            }
            #pragma unroll
            for (int mt = 0; mt < 2; mt++)
                #pragma unroll
                for (int nt = 0; nt < 8; nt++)
                    MMA_BF16(acc[mt][nt], af[mt], bf[nt][0], bf[nt][1]);
        }
    }

    #pragma unroll
    for (int mt = 0; mt < 2; mt++) {
        int row = by * 128 + wm + mt * 16 + (lane >> 2);
        int col = bx * 128 + wn + 2 * (lane & 3);
        #pragma unroll
        for (int nt = 0; nt < 8; nt++) {
            long i0 = (long)row * D_ + col + nt * 8;
            long i1 = i0 + 8 * D_;
            if (MODE == 2) {
                *(uint32_t*)&C16[i0] = pk_bf16x2(acc[mt][nt][0], acc[mt][nt][1]);
                *(uint32_t*)&C16[i1] = pk_bf16x2(acc[mt][nt][2], acc[mt][nt][3]);
            } else {
                float2 v0 = make_float2(acc[mt][nt][0], acc[mt][nt][1]);
                float2 v1 = make_float2(acc[mt][nt][2], acc[mt][nt][3]);
                if (MODE == 1) {
                    float2 r0 = *(const float2*)&resid[i0];
                    float2 r1 = *(const float2*)&resid[i1];
                    v0.x += r0.x; v0.y += r0.y;
                    v1.x += r1.x; v1.y += r1.y;
                }
                *(float2*)&C32[i0] = v0;
                *(float2*)&C32[i1] = v1;
            }
        }
    }
}

__global__ __launch_bounds__(256, 2) void gemm_qkv_kernel(
    const __nv_bfloat16* __restrict__ A,
    const __nv_bfloat16* __restrict__ Wq, const __nv_bfloat16* __restrict__ Wk,
    const __nv_bfloat16* __restrict__ Wv,
    float* __restrict__ hq, float* __restrict__ hk, __nv_bfloat16* __restrict__ v16)
{
    extern __shared__ __align__(16) char gsm[];
    int wsel = blockIdx.x >> 3;
    int bx = blockIdx.x & 7;
    if (wsel == 0)
        gemm128_bf16_core<0>(A, Wq, nullptr, hq, nullptr, blockIdx.y, bx, gsm);
    else if (wsel == 1)
        gemm128_bf16_core<0>(A, Wk, nullptr, hk, nullptr, blockIdx.y, bx, gsm);
    else
        gemm128_bf16_core<2>(A, Wv, nullptr, nullptr, v16, blockIdx.y, bx, gsm);
}

__global__ __launch_bounds__(256, 2) void gemm_o_kernel(
    const __nv_bfloat16* __restrict__ A, const __nv_bfloat16* __restrict__ W,
    const float* __restrict__ resid, float* __restrict__ C)
{
    extern __shared__ __align__(16) char gsm[];
    gemm128_bf16_core<1>(A, W, resid, C, nullptr, blockIdx.y, blockIdx.x, gsm);
}

// ---------------------------------------------------------------------------
// LoRA phase 1: z[row][:] = h[row] @ A   (grid: (M_/32, 2), 256 threads)
// ---------------------------------------------------------------------------
__global__ __launch_bounds__(256) void lora_z_kernel(
    const float* __restrict__ hq, const float* __restrict__ hk,
    const float* __restrict__ lora, float* __restrict__ z)
{
    int which = blockIdx.y;
    const float* h = which ? hk : hq;
    int rowBase = blockIdx.x * 32;
    int b = rowBase / S_;
    const float* Ag = lora + ((long)which * B_ + b) * D_ * R_;

    __shared__ float As[R_ * D_];
    int tid = threadIdx.x;
    int lane = tid & 31, w = tid >> 5;

    #pragma unroll
    for (int k = 0; k < 4; k++) {
        int d = tid + k * 256;
        float4 a0 = *(const float4*)&Ag[d * R_];
        float4 a1 = *(const float4*)&Ag[d * R_ + 4];
        As[0*D_+d] = a0.x; As[1*D_+d] = a0.y; As[2*D_+d] = a0.z; As[3*D_+d] = a0.w;
        As[4*D_+d] = a1.x; As[5*D_+d] = a1.y; As[6*D_+d] = a1.z; As[7*D_+d] = a1.w;
    }
    __syncthreads();

    #pragma unroll
    for (int rr = 0; rr < 4; rr++) {
        int row = rowBase + w * 4 + rr;
        const float* hrow = h + (long)row * D_;
        float part[R_];
        #pragma unroll
        for (int r = 0; r < R_; r++) part[r] = 0.f;
        #pragma unroll
        for (int k = 0; k < 32; k++) {
            int d = lane + k * 32;
            float hv = hrow[d];
            #pragma unroll
            for (int r = 0; r < R_; r++) part[r] += hv * As[r * D_ + d];
        }
        #pragma unroll
        for (int r = 0; r < R_; r++)
            #pragma unroll
            for (int o = 16; o > 0; o >>= 1)
                part[r] += __shfl_xor_sync(FULLMASK, part[r], o);
        if (lane == 0) {
            #pragma unroll
            for (int r = 0; r < R_; r++)
                z[((long)which * M_ + row) * R_ + r] = part[r];
        }
    }
}

// ---------------------------------------------------------------------------
// LoRA phase 2: g16 = bf16(h + 2*z@B^T). Grid (M_/16, 2), 256 threads.
// ---------------------------------------------------------------------------
#define LAR 16
__global__ __launch_bounds__(256) void lora_apply_kernel(
    const float* __restrict__ hq, const float* __restrict__ hk,
    __nv_bfloat16* __restrict__ q16, __nv_bfloat16* __restrict__ k16,
    const float* __restrict__ lora, const float* __restrict__ z)
{
    int which = blockIdx.y;
    const float* h = which ? hk : hq;
    __nv_bfloat16* g16 = which ? k16 : q16;
    int rowBase = blockIdx.x * LAR;
    int b = rowBase / S_;
    const float* Bg = lora + ((long)(2 + which) * B_ + b) * D_ * R_;

    __shared__ float zs[LAR][R_];
    int tid = threadIdx.x;
    if (tid < LAR * R_)
        zs[tid >> 3][tid & 7] = z[((long)which * M_ + rowBase + (tid >> 3)) * R_ + (tid & 7)];
    __syncthreads();

    int d0 = tid * 4;
    float br[4][R_];
    #pragma unroll
    for (int j = 0; j < 4; j++) {
        float4 b0 = *(const float4*)&Bg[(d0 + j) * R_];
        float4 b1 = *(const float4*)&Bg[(d0 + j) * R_ + 4];
        br[j][0] = b0.x; br[j][1] = b0.y; br[j][2] = b0.z; br[j][3] = b0.w;
        br[j][4] = b1.x; br[j][5] = b1.y; br[j][6] = b1.z; br[j][7] = b1.w;
    }

    #pragma unroll 4
    for (int rr = 0; rr < LAR; rr++) {
        long idx = (long)(rowBase + rr) * D_ + d0;
        float4 hv = *(const float4*)&h[idx];
        float del[4];
        #pragma unroll
        for (int j = 0; j < 4; j++) {
            float s = 0.f;
            #pragma unroll
            for (int r = 0; r < R_; r++) s += zs[rr][r] * br[j][r];
            del[j] = s;
        }
        uint2 o2;
        o2.x = pk_bf16x2(hv.x + 2.f * del[0], hv.y + 2.f * del[1]);
        o2.y = pk_bf16x2(hv.z + 2.f * del[2], hv.w + 2.f * del[3]);
        *(uint2*)&g16[idx] = o2;
    }
}

// ---------------------------------------------------------------------------
// Flash attention, bf16 mma, causal. Q tile 64, K/V tile 64, 128 threads,
// 3 CTAs/SM. P in registers. Mask only on diag tile. ex2.approx softmax,
// l-sum over unrounded exp values.
// ---------------------------------------------------------------------------
#define RB 144
#define KSLOT_B (64 * RB)
#define FQ_B  (64 * RB)
#define FLASH_SMEM (FQ_B + 3*KSLOT_B + 3*KSLOT_B)   // 64512

__global__ __launch_bounds__(128, 3) void flash_mma_kernel(
    const __nv_bfloat16* __restrict__ Q, const __nv_bfloat16* __restrict__ K,
    const __nv_bfloat16* __restrict__ V, __nv_bfloat16* __restrict__ O16)
{
    extern __shared__ __align__(16) char smc[];
    const uint32_t qsB = smem_u32(smc);
    const uint32_t ksB = qsB + FQ_B;
    const uint32_t vnB = ksB + 3 * KSLOT_B;

    int qi = (gridDim.x - 1) - blockIdx.x;   // heavy tiles first
    int h  = blockIdx.y;
    int b  = blockIdx.z;
    int tid = threadIdx.x;
    int lane = tid & 31;
    int w = tid >> 5;

    int cKp[4], cC[4];
    #pragma unroll
    for (int l = 0; l < 4; l++) {
        int idx = tid + l * 128;
        cKp[l] = idx >> 3; cC[l] = idx & 7;
    }

    const __nv_bfloat16* Qp = Q + (long)(b * S_ + qi * 64) * D_ + h * DH_;
    #pragma unroll
    for (int l = 0; l < 4; l++) {
        int idx = tid + l * 128;
        int q = idx >> 3, c8 = idx & 7;
        float4 v = *(const float4*)&Qp[(long)q * D_ + c8 * 8];
        asm volatile("st.shared.v4.b32 [%0], {%1,%2,%3,%4};" ::
            "r"(qsB + q * RB + c8 * 16),
            "r"(__float_as_uint(v.x)), "r"(__float_as_uint(v.y)),
            "r"(__float_as_uint(v.z)), "r"(__float_as_uint(v.w)) : "memory");
    }
    {
        const __nv_bfloat16* Kp = K + (long)(b * S_) * D_ + h * DH_;
        const __nv_bfloat16* Vp = V + (long)(b * S_) * D_ + h * DH_;
        #pragma unroll
        for (int l = 0; l < 4; l++) {
            CP16(ksB + cKp[l] * RB + cC[l] * 16, Kp + (long)cKp[l] * D_ + cC[l] * 8);
            CP16(vnB + cKp[l] * RB + cC[l] * 16, Vp + (long)cKp[l] * D_ + cC[l] * 8);
        }
        CP_COMMIT();
    }

    float o[8][4];
    #pragma unroll
    for (int nt = 0; nt < 8; nt++)
        #pragma unroll
        for (int j = 0; j < 4; j++) o[nt][j] = 0.f;
    float m0 = -1e30f, m1 = -1e30f, l0 = 0.f, l1 = 0.f;

    const uint32_t kFragOff = ((lane & 7) + ((lane >> 4) << 3)) * RB + ((lane >> 3) & 1) * 16;
    const uint32_t vFragOff = ((lane & 7) + ((lane >> 3) & 1) * 8) * RB + (lane >> 4) * 16;

    bool qfLoaded = false;
    uint32_t qf[4][4];

    const float SC = 0.125f * 1.44269504f;   // scale * log2(e)
    int ktmax = qi + 1;

    // Tile body; MASK is a compile-time bool via integral_constant.
    auto tile_body = [&](int kt, auto maskc) {
        constexpr bool MASK = decltype(maskc)::value;
        int slot = kt % 3;
        bool havenext = (kt + 1) < ktmax;

        if (havenext) {
            int ns = (kt + 1) % 3;
            const __nv_bfloat16* Kp = K + (long)(b * S_ + (kt + 1) * 64) * D_ + h * DH_;
            const __nv_bfloat16* Vp = V + (long)(b * S_ + (kt + 1) * 64) * D_ + h * DH_;
            uint32_t kd = ksB + ns * KSLOT_B, vd = vnB + ns * KSLOT_B;
            #pragma unroll
            for (int l = 0; l < 4; l++) {
                CP16(kd + cKp[l] * RB + cC[l] * 16, Kp + (long)cKp[l] * D_ + cC[l] * 8);
                CP16(vd + cKp[l] * RB + cC[l] * 16, Vp + (long)cKp[l] * D_ + cC[l] * 8);
            }
            CP_COMMIT();
            CP_WAIT(1);
        } else {
            CP_WAIT(0);
        }
        __syncthreads();

        if (!qfLoaded) {
            uint32_t base = qsB + (w * 16 + (lane & 15)) * RB + (lane >> 4) * 16;
            #pragma unroll
            for (int ds = 0; ds < 4; ds++)
                LDSM4(qf[ds][0], qf[ds][1], qf[ds][2], qf[ds][3], base + ds * 32);
            qfLoaded = true;
        }

        const uint32_t kBase = ksB + slot * KSLOT_B + kFragOff;
        const uint32_t vBase = vnB + slot * KSLOT_B + vFragOff;

        // ---- S = Q K^T ----
        float s[8][4];
        #pragma unroll
        for (int nt = 0; nt < 8; nt++)
            #pragma unroll
            for (int j = 0; j < 4; j++) s[nt][j] = 0.f;

        #pragma unroll
        for (int ds = 0; ds < 4; ds++) {
            uint32_t bf[8][2];
            #pragma unroll
            for (int ntp = 0; ntp < 4; ntp++) {
                uint32_t r0, r1, r2, r3;
                LDSM4(r0, r1, r2, r3, kBase + ntp * 16 * RB + ds * 32);
                bf[2 * ntp][0] = r0; bf[2 * ntp][1] = r1;
                bf[2 * ntp + 1][0] = r2; bf[2 * ntp + 1][1] = r3;
            }
            #pragma unroll
            for (int nt = 0; nt < 8; nt++)
                MMA_BF16(s[nt], qf[ds], bf[nt][0], bf[nt][1]);
        }

        // ---- scale (+ mask on diag tile) + online softmax (ex2.approx) ----
        float ml0 = -1e30f, ml1 = -1e30f;
        #pragma unroll
        for (int nt = 0; nt < 8; nt++) {
            #pragma unroll
            for (int j = 0; j < 4; j++) {
                float v = s[nt][j] * SC;
                if (MASK) {
                    int col = kt * 64 + nt * 8 + 2 * (lane & 3) + (j & 1);
                    int row = qi * 64 + w * 16 + (lane >> 2) + ((j >> 1) << 3);
                    if (col > row) v = -1e30f;
                }
                s[nt][j] = v;
            }
            ml0 = fmaxf(ml0, fmaxf(s[nt][0], s[nt][1]));
            ml1 = fmaxf(ml1, fmaxf(s[nt][2], s[nt][3]));
        }
        ml0 = fmaxf(ml0, __shfl_xor_sync(FULLMASK, ml0, 1));
        ml0 = fmaxf(ml0, __shfl_xor_sync(FULLMASK, ml0, 2));
        ml1 = fmaxf(ml1, __shfl_xor_sync(FULLMASK, ml1, 1));
        ml1 = fmaxf(ml1, __shfl_xor_sync(FULLMASK, ml1, 2));
        float mn0 = fmaxf(m0, ml0), mn1 = fmaxf(m1, ml1);
        float a0 = ex2(m0 - mn0), a1 = ex2(m1 - mn1);
        float sum0 = 0.f, sum1 = 0.f;
        #pragma unroll
        for (int nt = 0; nt < 8; nt++) {
            s[nt][0] = ex2(s[nt][0] - mn0);
            s[nt][1] = ex2(s[nt][1] - mn0);
            s[nt][2] = ex2(s[nt][2] - mn1);
            s[nt][3] = ex2(s[nt][3] - mn1);
            sum0 += s[nt][0] + s[nt][1];
            sum1 += s[nt][2] + s[nt][3];
        }
        sum0 += __shfl_xor_sync(FULLMASK, sum0, 1);
        sum0 += __shfl_xor_sync(FULLMASK, sum0, 2);
        sum1 += __shfl_xor_sync(FULLMASK, sum1, 1);
        sum1 += __shfl_xor_sync(FULLMASK, sum1, 2);
        l0 = l0 * a0 + sum0;
        l1 = l1 * a1 + sum1;
        m0 = mn0; m1 = mn1;
        #pragma unroll
        for (int nt = 0; nt < 8; nt++) {
            o[nt][0] *= a0; o[nt][1] *= a0;
            o[nt][2] *= a1; o[nt][3] *= a1;
        }

        // ---- O += P V : P A-frags packed directly from S C-frags ----
        #pragma unroll
        for (int ks = 0; ks < 4; ks++) {
            uint32_t pf[4];
            pf[0] = pk_bf16x2(s[2*ks][0],   s[2*ks][1]);
            pf[1] = pk_bf16x2(s[2*ks][2],   s[2*ks][3]);
            pf[2] = pk_bf16x2(s[2*ks+1][0], s[2*ks+1][1]);
            pf[3] = pk_bf16x2(s[2*ks+1][2], s[2*ks+1][3]);
            uint32_t vf[8][2];
            #pragma unroll
            for (int ntp = 0; ntp < 4; ntp++) {
                uint32_t r0, r1, r2, r3;
                LDSM4T(r0, r1, r2, r3, vBase + ks * 16 * RB + ntp * 32);
                vf[2 * ntp][0] = r0; vf[2 * ntp][1] = r1;
                vf[2 * ntp + 1][0] = r2; vf[2 * ntp + 1][1] = r3;
            }
            #pragma unroll
            for (int nt = 0; nt < 8; nt++)
                MMA_BF16(o[nt], pf, vf[nt][0], vf[nt][1]);
        }
    };

    // Off-diagonal tiles: mask provably never fires (col < qi*64 <= row).
    for (int kt = 0; kt < ktmax - 1; kt++)
        tile_body(kt, std::integral_constant<bool, false>{});
    // Diagonal tile (kt == qi): masked.
    tile_body(ktmax - 1, std::integral_constant<bool, true>{});

    // normalize + write bf16
    float inv0 = 1.f / l0, inv1 = 1.f / l1;
    int row0 = qi * 64 + w * 16 + (lane >> 2);
    long base0 = (long)(b * S_ + row0) * D_ + h * DH_ + 2 * (lane & 3);
    long base1 = base0 + 8 * D_;
    #pragma unroll
    for (int nt = 0; nt < 8; nt++) {
        *(uint32_t*)&O16[base0 + nt * 8] = pk_bf16x2(o[nt][0] * inv0, o[nt][1] * inv0);
        *(uint32_t*)&O16[base1 + nt * 8] = pk_bf16x2(o[nt][2] * inv1, o[nt][3] * inv1);
    }
}

// ---------------------------------------------------------------------------
// Launch
// ---------------------------------------------------------------------------
extern "C" void kernel_launch(void* const* d_in, const int* in_sizes, int n_in,
                              void* d_out, int out_size)
{
    const float* hidden = (const float*)d_in[0];
    // d_in[1] = attention_mask: causal tril -> handled analytically
    const float* lora   = (const float*)d_in[2];   // [4, B, D, R]
    const float* ln_w   = (const float*)d_in[3];
    const float* Wq     = (const float*)d_in[4];
    const float* Wk     = (const float*)d_in[5];
    const float* Wv     = (const float*)d_in[6];
    const float* Wo     = (const float*)d_in[7];
    float* out = (float*)d_out;

    float *hq, *hk, *z;
    __nv_bfloat16 *x16, *q16, *k16, *v16, *attn16, *wq16, *wk16, *wv16, *wo16;
    cudaGetSymbolAddress((void**)&x16,    g_x16);
    cudaGetSymbolAddress((void**)&hq,     g_hq);
    cudaGetSymbolAddress((void**)&hk,     g_hk);
    cudaGetSymbolAddress((void**)&z,      g_z);
    cudaGetSymbolAddress((void**)&q16,    g_q16);
    cudaGetSymbolAddress((void**)&k16,    g_k16);
    cudaGetSymbolAddress((void**)&v16,    g_v16);
    cudaGetSymbolAddress((void**)&attn16, g_attn16);
    cudaGetSymbolAddress((void**)&wq16,   g_wq16);
    cudaGetSymbolAddress((void**)&wk16,   g_wk16);
    cudaGetSymbolAddress((void**)&wv16,   g_wv16);
    cudaGetSymbolAddress((void**)&wo16,   g_wo16);

    cudaFuncSetAttribute(gemm_qkv_kernel, cudaFuncAttributeMaxDynamicSharedMemorySize, GEMM_SMEM);
    cudaFuncSetAttribute(gemm_o_kernel,   cudaFuncAttributeMaxDynamicSharedMemorySize, GEMM_SMEM);
    cudaFuncSetAttribute(flash_mma_kernel, cudaFuncAttributeMaxDynamicSharedMemorySize, FLASH_SMEM);

    // 0+1. RMSNorm (-> bf16) + weight conversion
    prep_kernel<<<M_ + 2048, 256>>>(hidden, ln_w, Wq, Wk, Wv, Wo,
                                    x16, wq16, wk16, wv16, wo16);

    // 2. Fused QKV projections (q/k out fp32 for LoRA, V out bf16)
    dim3 gq(24, M_ / 128);
    gemm_qkv_kernel<<<gq, 256, GEMM_SMEM>>>(x16, wq16, wk16, wv16, hq, hk, v16);

    // 3. LoRA: z = h@A, then h += 2 z@B^T -> bf16
    dim3 gl(M_ / 32, 2);
    lora_z_kernel<<<gl, 256>>>(hq, hk, lora, z);
    dim3 gla(M_ / LAR, 2);
    lora_apply_kernel<<<gla, 256>>>(hq, hk, q16, k16, lora, z);

    // 4. Causal flash attention (bf16 in/out, Q-tile 64, 128 threads, reg-P)
    dim3 fg(S_ / 64, H_, B_);
    flash_mma_kernel<<<fg, 128, FLASH_SMEM>>>(q16, k16, v16, attn16);

    // 5. Output projection + residual (bf16 in, fp32 out)
    dim3 go(8, M_ / 128);
    gemm_o_kernel<<<go, 256, GEMM_SMEM>>>(attn16, wo16, hidden, out);
}